// round 13
// baseline (speedup 1.0000x reference)
#include <cuda_runtime.h>
#include <math.h>

#define BN 40000
#define NV 10000
#define TT 12
#define NE 160000
#define BNT (BN*TT)
#define OFS 30720000
#define NB 4
#define QST 200
#define SMEM_M1 53248
typedef unsigned long long ull;

// ---------------- device scratch (static, no allocations) ----------------
static __device__ int   d_deg[NV], d_cnt[NV], d_rs[NV], d_re[NV], d_cursor[NV];
static __device__ int   d_tot;
static __device__ float d_dis[NV];
static __device__ __align__(16) int2  d_ewi[NE];     // {src*12, bitcast(weight)} segment order
static __device__ __align__(16) float d_T1[BNT];
static __device__ __align__(16) float d_attc[16];
static __device__ __align__(16) float4 d_pack[BNT*2]; // {aS0,aS1,T0,T1},{T2,aD0,aD1,0}
static __device__ __align__(16) float4 d_G8[BNT*2];   // {g0..g3},{g4,g5,0,0}
static __device__ __align__(16) float d_P2[3456];     // [dt][r][j] j contiguous
static __device__ __align__(16) float d_Cq[576], d_Bq[192];
static __device__ __align__(16) float d_cwi[24576];   // [(c*3+dt)][o*2 + {bc,fc}]
static __device__ __align__(16) float d_cb[128];
static __device__ __align__(16) float d_owt[4096];    // [i=c/2][f][2] out_w pair-transposed
static __device__ __align__(16) float d_R[BNT*64];    // [bn][t][f]

__device__ __forceinline__ float lrelu(float x){ return x >= 0.f ? x : 0.2f*x; }
__device__ __forceinline__ ull pk2(float a, float b){ ull r; asm("mov.b64 %0,{%1,%2};" : "=l"(r) : "f"(a), "f"(b)); return r; }
__device__ __forceinline__ void fma2(ull& d, ull a, ull b){ asm("fma.rn.f32x2 %0,%1,%2,%0;" : "+l"(d) : "l"(a), "l"(b)); }
__device__ __forceinline__ float2 up2(ull v){ float2 r; asm("mov.b64 {%0,%1},%2;" : "=f"(r.x), "=f"(r.y) : "l"(v)); return r; }

// ---------------- graph preprocessing ----------------
__global__ void k_count(const int* __restrict__ ei){
  int e = blockIdx.x*blockDim.x + threadIdx.x;
  if(e < NE){
    atomicAdd(&d_deg[ei[e]], 1);
    atomicAdd(&d_cnt[ei[NE+e]], 1);
  }
}

// parallel (unordered) CSR segment assignment + deg^{-1/2}
__global__ void k_off(){
  int i = blockIdx.x*blockDim.x + threadIdx.x;
  int lane = threadIdx.x & 31;
  int c = (i < NV) ? d_cnt[i] : 0;
  int pre = c;
  #pragma unroll
  for(int off=1; off<32; off<<=1){
    int v = __shfl_up_sync(0xFFFFFFFFu, pre, off);
    if(lane >= off) pre += v;
  }
  int tot = __shfl_sync(0xFFFFFFFFu, pre, 31);
  int base = 0;
  if(lane == 31) base = atomicAdd(&d_tot, tot);
  base = __shfl_sync(0xFFFFFFFFu, base, 31);
  if(i < NV){
    int start = base + pre - c;
    d_rs[i] = start; d_cursor[i] = start; d_re[i] = start + c;
    int dg = d_deg[i];
    d_dis[i] = (dg > 0) ? 1.0f/sqrtf((float)dg) : 0.0f;
  }
}

__global__ void k_fill(const int* __restrict__ ei){
  int e = blockIdx.x*blockDim.x + threadIdx.x;
  if(e < NE){
    int s = ei[e], d = ei[NE+e];
    float w = -d_dis[s]*d_dis[d];
    int p = atomicAdd(&d_cursor[d], 1);
    d_ewi[p] = make_int2(s*12, __float_as_int(w));
  }
}

// ---------------- weight folding (+ counter zeroing) ----------------
__global__ void k_prep(const float* __restrict__ cheb_w, const float* __restrict__ cheb_b,
                       const float* __restrict__ gat_w,  const float* __restrict__ att_src,
                       const float* __restrict__ att_dst,const float* __restrict__ gat_b,
                       const float* __restrict__ tc_w,   const float* __restrict__ tc_b,
                       const float* __restrict__ in_w,   const float* __restrict__ in_b,
                       const float* __restrict__ outw,
                       const float* __restrict__ bcw,    const float* __restrict__ bcb,
                       const float* __restrict__ fcw,    const float* __restrict__ fcb){
  __shared__ float sV[3][128], sC0[128], sU[6][64], sSb[64], sUW[6*192], sSbW[192];
  int tid = threadIdx.x;
  for(int i=tid; i<NV; i+=256){ d_deg[i] = 0; d_cnt[i] = 0; }
  if(tid == 0) d_tot = 0;
  for(int idx=tid; idx<512; idx+=256){
    int k = idx>>7, r = idx&127;
    const float* wv = (k<3)? &cheb_w[k*64] : cheb_b;
    float s = 0.f;
    for(int c=0;c<64;c++) s += wv[c]*gat_w[r*64+c];
    if(k<3) sV[k][r]=s; else sC0[r]=s;
  }
  __syncthreads();
  if(tid < 16){
    int which = tid/8, k = (tid%8)/2, h = tid%2;
    const float* att = which ? att_dst : att_src;
    const float* vv  = (k<3) ? sV[k] : sC0;
    float s = 0.f;
    for(int c=0;c<64;c++) s += vv[h*64+c]*att[h*64+c];
    d_attc[tid] = s;
  }
  for(int idx=tid; idx<6*64; idx+=256){
    int j = idx/64, c = idx%64, h = j/3, k = j%3;
    sU[j][c] = 0.5f*sV[k][h*64+c];
  }
  if(tid < 64) sSb[tid] = gat_b[tid] + 0.5f*(sC0[tid] + sC0[64+tid]);
  __syncthreads();
  for(int idx=tid; idx<7*192; idx+=256){
    int j = idx/192, od = idx%192, o = od/3, dt = od%3;
    const float* uu = (j<6) ? sU[j] : sSb;
    float s = 0.f;
    for(int c=0;c<64;c++) s += uu[c]*tc_w[o*192 + c*3 + dt];
    if(j<6) sUW[j*192+od] = s; else sSbW[od] = s;
  }
  __syncthreads();
  for(int idx=tid; idx<3456; idx+=256){
    int j = idx%6; int rr = (idx/6)%192; int dt = idx/1152;
    float s = 0.f;
    for(int o=0;o<64;o++) s += in_w[rr*64+o]*sUW[j*192 + o*3 + dt];
    d_P2[idx] = s;
  }
  for(int idx=tid; idx<576; idx+=256){
    int dt = idx/192, r = idx%192;
    float s = 0.f;
    for(int o=0;o<64;o++) s += in_w[r*64+o]*sSbW[o*3+dt];
    d_Cq[idx] = s;
  }
  for(int idx=tid; idx<192; idx+=256){
    float s = in_b[idx];
    for(int o=0;o<64;o++) s += in_w[idx*64+o]*tc_b[o];
    d_Bq[idx] = s;
  }
  // conv weights interleaved: d_cwi[(c*3+dt)*128 + o*2 + j] = (j? fcw : bcw)[o][c][dt]
  for(int idx=tid; idx<24576; idx+=256){
    int j = idx&1, o = (idx>>1)&63, cd = idx>>7;
    int c = cd/3, dt = cd - 3*c;
    d_cwi[idx] = j ? fcw[o*192 + c*3 + dt] : bcw[o*192 + c*3 + dt];
  }
  if(tid < 128) d_cb[tid] = (tid < 64) ? bcb[tid] : fcb[tid-64];
  // out_w pair-transposed
  for(int idx=tid; idx<4096; idx+=256){
    int j = idx&1, rest = idx>>1, f = rest&63, i = rest>>6;
    d_owt[idx] = outw[f*64 + 2*i + j];
  }
}

// ---------------- Cheb prop (t-pairs) ----------------
__global__ void k_prop1(const float* __restrict__ x0){
  int i = blockIdx.x*blockDim.x + threadIdx.x;
  if(i >= BN*6) return;
  int bn = i/6, tp = i - bn*6;
  float sx = 0.f, sy = 0.f;
  if(bn < NV){
    int b = d_rs[bn], en = d_re[bn];
    for(int j=b;j<en;j++){
      int2 er = d_ewi[j];
      float w = __int_as_float(er.y);
      float2 xv = *(const float2*)&x0[er.x + 2*tp];
      sx += w*xv.x; sy += w*xv.y;
    }
  }
  *(float2*)&d_T1[bn*12 + 2*tp] = make_float2(sx, sy);
}

// prop2 + attention logits + pack (fused)
__global__ void k_prop2p(const float* __restrict__ x0){
  int i = blockIdx.x*blockDim.x + threadIdx.x;
  if(i >= BN*6) return;
  int bn = i/6, tp = i - bn*6;
  float sx = 0.f, sy = 0.f;
  if(bn < NV){
    int b = d_rs[bn], en = d_re[bn];
    for(int j=b;j<en;j++){
      int2 er = d_ewi[j];
      float w = __int_as_float(er.y);
      float2 tv = *(const float2*)&d_T1[er.x + 2*tp];
      sx += w*tv.x; sy += w*tv.y;
    }
  }
  int i0 = bn*12 + 2*tp;
  float2 xp  = *(const float2*)&x0[i0];
  float2 t1p = *(const float2*)&d_T1[i0];
  float t2a = 2.f*sx - xp.x, t2b = 2.f*sy - xp.y;
  float4 c0 = *(const float4*)&d_attc[0];
  float4 c1 = *(const float4*)&d_attc[4];
  float4 c2 = *(const float4*)&d_attc[8];
  float4 c3 = *(const float4*)&d_attc[12];
  {
    float t0 = xp.x, t1 = t1p.x, t2 = t2a;
    float aS0 = c1.z + t0*c0.x + t1*c0.z + t2*c1.x;
    float aS1 = c1.w + t0*c0.y + t1*c0.w + t2*c1.y;
    float aD0 = c3.z + t0*c2.x + t1*c2.z + t2*c3.x;
    float aD1 = c3.w + t0*c2.y + t1*c2.w + t2*c3.y;
    d_pack[i0*2+0] = make_float4(aS0, aS1, t0, t1);
    d_pack[i0*2+1] = make_float4(t2, aD0, aD1, 0.f);
  }
  {
    float t0 = xp.y, t1 = t1p.y, t2 = t2b;
    float aS0 = c1.z + t0*c0.x + t1*c0.z + t2*c1.x;
    float aS1 = c1.w + t0*c0.y + t1*c0.w + t2*c1.y;
    float aD0 = c3.z + t0*c2.x + t1*c2.z + t2*c3.x;
    float aD1 = c3.w + t0*c2.y + t1*c2.w + t2*c3.y;
    d_pack[(i0+1)*2+0] = make_float4(aS0, aS1, t0, t1);
    d_pack[(i0+1)*2+1] = make_float4(t2, aD0, aD1, 0.f);
  }
}

// ---------------- GAT: single-pass softmax aggregation ----------------
__global__ void k_gat(){
  int i = blockIdx.x*blockDim.x + threadIdx.x;
  if(i >= BNT) return;
  int bn = i/12, t = i - bn*12;
  float4 pa = d_pack[i*2], pb = d_pack[i*2+1];
  float aD0 = pb.y, aD1 = pb.z;
  float e0 = __expf(lrelu(pa.x + aD0));
  float e1 = __expf(lrelu(pa.y + aD1));
  float z0 = e0, z1 = e1;
  float a00 = e0*pa.z, a01 = e0*pa.w, a02 = e0*pb.x;
  float a10 = e1*pa.z, a11 = e1*pa.w, a12 = e1*pb.x;
  if(bn < NV){
    int b = d_rs[bn], en = d_re[bn];
    for(int j=b;j<en;j++){
      int2 er = d_ewi[j];
      int si = er.x + t;
      float4 na = d_pack[si*2], nb = d_pack[si*2+1];
      float q0 = __expf(lrelu(na.x + aD0));
      float q1 = __expf(lrelu(na.y + aD1));
      z0 += q0; a00 += q0*na.z; a01 += q0*na.w; a02 += q0*nb.x;
      z1 += q1; a10 += q1*na.z; a11 += q1*na.w; a12 += q1*nb.x;
    }
  }
  float iz0 = 1.f/z0, iz1 = 1.f/z1;
  d_G8[i*2+0] = make_float4(a00*iz0, a01*iz0, a02*iz0, a10*iz1);
  d_G8[i*2+1] = make_float4(a11*iz1, a12*iz1, 0.f, 0.f);
}

// ---------------- per-node-group mega kernel (4 nodes/block, dynamic smem) ----------------
__global__ void __launch_bounds__(192,2) k_m1(
    const float* __restrict__ x0,
    const float* __restrict__ outb,const float* __restrict__ resw,
    const float* __restrict__ resb,const float* __restrict__ lng,
    const float* __restrict__ lnb){
  extern __shared__ __align__(16) char dsm[];
  float* qs   = (float*)dsm;
  float* zsh  = (float*)dsm;                 // alias: qs dead after MHA
  float* osh  = (float*)(dsm + 38400);
  float (*a6p)[14][8] = (float(*)[14][8])(dsm + 50688);
  float* xs   = (float*)(dsm + 52480);
  float* mu   = (float*)(dsm + 52672);
  float* rstd = (float*)(dsm + 52864);

  int bn0 = blockIdx.x*NB;
  int tid = threadIdx.x;

  for(int i=tid; i<NB*112; i+=192){
    int n = i/112, rr = (i%112)>>3, col = i&7;
    a6p[n][rr][col] = (rr==0 || rr==13) ? 0.f
                    : ((const float*)d_G8)[(size_t)(bn0+n)*96 + (rr-1)*8 + col];
  }
  if(tid < NB*12) xs[tid] = x0[bn0*12 + tid];

  int r = tid;
  ull P2r[9];
  #pragma unroll
  for(int dt=0;dt<3;dt++)
    #pragma unroll
    for(int jj=0;jj<3;jj++)
      P2r[dt*3+jj] = *(const ull*)&d_P2[(dt*192+r)*6 + jj*2];
  float bq = d_Bq[r], cq0 = d_Cq[r], cq1 = d_Cq[192+r], cq2 = d_Cq[384+r];
  float cB = bq+cq1+cq2, cI = bq+cq0+cq1+cq2, cE = bq+cq0+cq1;
  __syncthreads();

  #pragma unroll
  for(int n=0;n<NB;n++){
    #pragma unroll
    for(int t=0;t<12;t++){
      ull acc = 0ULL;
      const ull* a0 = (const ull*)a6p[n][t];
      const ull* a1 = (const ull*)a6p[n][t+1];
      const ull* a2 = (const ull*)a6p[n][t+2];
      fma2(acc, P2r[0], a0[0]); fma2(acc, P2r[1], a0[1]); fma2(acc, P2r[2], a0[2]);
      fma2(acc, P2r[3], a1[0]); fma2(acc, P2r[4], a1[1]); fma2(acc, P2r[5], a1[2]);
      fma2(acc, P2r[6], a2[0]); fma2(acc, P2r[7], a2[1]); fma2(acc, P2r[8], a2[2]);
      float2 u = up2(acc);
      qs[n*2400 + t*QST + r] = u.x + u.y + (t==0 ? cB : (t==11 ? cE : cI));
    }
  }
  __syncthreads();

  {
    int n = tid/48, rem = tid%48, h = rem/12, tq = rem%12;
    const float* qbase = &qs[n*2400];
    const ull* qv = (const ull*)&qbase[tq*QST + h*16];
    ull qr[8];
    #pragma unroll
    for(int d=0;d<8;d++) qr[d] = qv[d];
    float sc[12]; float m = -1e30f;
    #pragma unroll
    for(int tk=0;tk<12;tk++){
      const ull* kv = (const ull*)&qbase[tk*QST + 64 + h*16];
      ull a = 0ULL;
      #pragma unroll
      for(int d=0;d<8;d++) fma2(a, qr[d], kv[d]);
      float2 u = up2(a);
      float s = (u.x+u.y)*0.25f;
      sc[tk] = s; m = fmaxf(m, s);
    }
    float z = 0.f;
    #pragma unroll
    for(int tk=0;tk<12;tk++){ sc[tk] = __expf(sc[tk]-m); z += sc[tk]; }
    float inv = 1.f/z;
    ull o2[8];
    #pragma unroll
    for(int d=0;d<8;d++) o2[d] = 0ULL;
    #pragma unroll
    for(int tk=0;tk<12;tk++){
      ull sp = pk2(sc[tk], sc[tk]);
      const ull* vv = (const ull*)&qbase[tk*QST + 128 + h*16];
      #pragma unroll
      for(int d=0;d<8;d++) fma2(o2[d], sp, vv[d]);
    }
    #pragma unroll
    for(int d=0;d<8;d++){
      float2 u = up2(o2[d]);
      *(float2*)&osh[n*768 + tq*64 + h*16 + 2*d] = make_float2(u.x*inv, u.y*inv);
    }
  }

  int f = tid%64, grp = tid/64;
  ull wreg[32];
  #pragma unroll
  for(int i=0;i<32;i++) wreg[i] = *(const ull*)&d_owt[(i*64+f)*2];
  float obf = outb[f], rwf = resw[f], rbf = resb[f];
  __syncthreads();            // MHA done; qs dead -> zsh alias safe

  // out projection: longlong2 loads give aligned reg pairs -> no packing MOVs
  #pragma unroll
  for(int it=0; it<16; it++){
    int pi = grp*16 + it;
    int n = pi/12, t = pi%12;
    const longlong2* op2 = (const longlong2*)&osh[n*768 + t*64];
    ull acc = 0ULL;
    #pragma unroll
    for(int i=0;i<16;i++){
      longlong2 q = op2[i];
      fma2(acc, (ull)q.x, wreg[2*i]);
      fma2(acc, (ull)q.y, wreg[2*i+1]);
    }
    float2 u = up2(acc);
    float v = u.x + u.y + obf + rwf*xs[pi] + rbf;
    zsh[pi*64 + f] = fmaxf(v, 0.f);
  }
  __syncthreads();

  if(tid < NB*12){
    const float* zr = &zsh[tid*64];
    float s = 0.f;
    for(int ff=0;ff<64;ff++) s += zr[ff];
    float mm = s*(1.f/64.f);
    float v = 0.f;
    for(int ff=0;ff<64;ff++){ float d = zr[ff]-mm; v += d*d; }
    mu[tid] = mm; rstd[tid] = rsqrtf(v*(1.f/64.f) + 1e-5f);
  }
  __syncthreads();

  float lgf = lng[f], lbf = lnb[f];
  #pragma unroll
  for(int it=0; it<16; it++){
    int pi = grp*16 + it;
    d_R[(size_t)bn0*768 + pi*64 + f] = (zsh[pi*64+f]-mu[pi])*rstd[pi]*lgf + lbf;
  }
}

// ---------------- backcast/forecast convs: (bc,fc) packed in f32x2 halves ----------------
// (R10 proven version) thread = (node nn, channel o). Values duplicated in smem
// -> LDS.64 broadcast, weights pre-interleaved (bc,fc) -> LDG.64. No packing MOVs.
__global__ void __launch_bounds__(256) k_m2(float* __restrict__ out){
  __shared__ __align__(16) float rsd[4*64*30];   // 30720 B
  int tid = threadIdx.x;
  int node0 = blockIdx.x*4;

  {  // zero pad slots (t=-1, t=12)
    int nn = tid>>6, c = tid&63;
    float* rw = &rsd[(nn*64+c)*30];
    *(ull*)&rw[0]  = 0ULL;
    *(ull*)&rw[26] = 0ULL;
  }
  for(int v=tid; v<3072; v+=256){
    int nn = v/768, rm = v-nn*768, t = rm>>6, c = rm&63;
    float q = d_R[(size_t)(node0+nn)*768 + rm];
    *(ull*)&rsd[(nn*64+c)*30 + (t+1)*2] = pk2(q,q);
  }
  __syncthreads();

  int nn = tid>>6, o = tid&63;
  const float* rb = &rsd[nn*1920];
  ull acc[12];
  #pragma unroll
  for(int t=0;t<12;t++) acc[t]=0ULL;

  #pragma unroll 4
  for(int c=0;c<64;c++){
    const ull* wp = (const ull*)&d_cwi[(c*3)*128 + o*2];
    ull w0 = wp[0], w1 = wp[64], w2 = wp[128];
    const ull* vp = (const ull*)&rb[c*30];
    #pragma unroll
    for(int t=0;t<12;t++){
      fma2(acc[t], w0, vp[t]);      // r(t-1)
      fma2(acc[t], w1, vp[t+1]);    // r(t)
      fma2(acc[t], w2, vp[t+2]);    // r(t+1)
    }
  }

  int bn = node0 + nn;
  float b0 = d_cb[o], b1 = d_cb[64+o];
  float oa[12], ob[12];
  #pragma unroll
  for(int t=0;t<12;t++){
    float2 u = up2(acc[t]);
    oa[t] = u.x + b0;
    ob[t] = u.y + b1;
  }
  size_t bcb_ = (size_t)bn*768 + (size_t)o*12;
  size_t fcb_ = (size_t)OFS + bcb_;
  *(float4*)&out[bcb_+0] = make_float4(oa[0],oa[1],oa[2],oa[3]);
  *(float4*)&out[bcb_+4] = make_float4(oa[4],oa[5],oa[6],oa[7]);
  *(float4*)&out[bcb_+8] = make_float4(oa[8],oa[9],oa[10],oa[11]);
  *(float4*)&out[fcb_+0] = make_float4(ob[0],ob[1],ob[2],ob[3]);
  *(float4*)&out[fcb_+4] = make_float4(ob[4],ob[5],ob[6],ob[7]);
  *(float4*)&out[fcb_+8] = make_float4(ob[8],ob[9],ob[10],ob[11]);
}

// ---------------- launch ----------------
extern "C" void kernel_launch(void* const* d_in, const int* in_sizes, int n_in,
                              void* d_out, int out_size){
  const float* x       = (const float*)d_in[0];
  const int*   ei      = (const int*  )d_in[1];
  const float* cheb_w  = (const float*)d_in[2];
  const float* cheb_b  = (const float*)d_in[3];
  const float* gat_w   = (const float*)d_in[4];
  const float* att_src = (const float*)d_in[5];
  const float* att_dst = (const float*)d_in[6];
  const float* gat_b   = (const float*)d_in[7];
  const float* tc_w    = (const float*)d_in[8];
  const float* tc_b    = (const float*)d_in[9];
  const float* in_w    = (const float*)d_in[10];
  const float* in_b    = (const float*)d_in[11];
  const float* out_w   = (const float*)d_in[12];
  const float* out_b   = (const float*)d_in[13];
  const float* res_w   = (const float*)d_in[14];
  const float* res_b   = (const float*)d_in[15];
  const float* ln_g    = (const float*)d_in[16];
  const float* ln_b    = (const float*)d_in[17];
  const float* bc_w    = (const float*)d_in[18];
  const float* bc_b    = (const float*)d_in[19];
  const float* fc_w    = (const float*)d_in[20];
  const float* fc_b    = (const float*)d_in[21];
  float* out = (float*)d_out;

  cudaFuncSetAttribute(k_m1, cudaFuncAttributeMaxDynamicSharedMemorySize, SMEM_M1);

  k_prep  <<<1, 256>>>(cheb_w, cheb_b, gat_w, att_src, att_dst, gat_b,
                       tc_w, tc_b, in_w, in_b, out_w, bc_w, bc_b, fc_w, fc_b);
  k_count <<<(NE +255)/256, 256>>>(ei);
  k_off   <<<(NV +255)/256, 256>>>();
  // MEASUREMENT: dummy full-grid k_m1 at launch slot 4 (ncu capture window).
  // Reads stale/zero d_G8 and writes d_R garbage that the real k_m1 below
  // fully overwrites -> output remains deterministic. Cost: +T(k_m1) wall time.
  k_m1    <<<BN/NB, 192, SMEM_M1>>>(x, out_b, res_w, res_b, ln_g, ln_b);
  k_fill  <<<(NE +255)/256, 256>>>(ei);
  k_prop1 <<<(BN*6+255)/256, 256>>>(x);
  k_prop2p<<<(BN*6+255)/256, 256>>>(x);
  k_gat   <<<(BNT+255)/256, 256>>>();
  k_m1    <<<BN/NB, 192, SMEM_M1>>>(x, out_b, res_w, res_b, ln_g, ln_b);
  k_m2    <<<BN/4, 256>>>(out);
}

// round 15
// speedup vs baseline: 1.3459x; 1.3459x over previous
#include <cuda_runtime.h>
#include <math.h>

#define BN 40000
#define NV 10000
#define TT 12
#define NE 160000
#define BNT (BN*TT)
#define OFS 30720000
#define NB 4
#define QST 200
#define SMEM_M1 53248
typedef unsigned long long ull;

// ---------------- device scratch (static, no allocations) ----------------
static __device__ int   d_deg[NV], d_cnt[NV], d_rs[NV], d_re[NV], d_cursor[NV];
static __device__ int   d_tot;
static __device__ float d_dis[NV];
static __device__ __align__(16) int2  d_ewi[NE];     // {src*12, bitcast(weight)} segment order
static __device__ __align__(16) float d_T1[BNT];
static __device__ __align__(16) float d_attc[16];
static __device__ __align__(16) float4 d_pack[BNT*2]; // {aS0,aS1,T0,T1},{T2,aD0,aD1,0}
static __device__ __align__(16) float4 d_G8[BNT*2];   // {g0..g3},{g4,g5,0,0}
static __device__ __align__(16) float d_P2[3456];     // [dt][r][j] j contiguous
static __device__ __align__(16) float d_Cq[576], d_Bq[192];
static __device__ __align__(16) float d_cwi[24576];   // [(c*3+dt)][o*2 + {bc,fc}]
static __device__ __align__(16) float d_cb[128];
static __device__ __align__(16) float d_owt[4096];    // [i=c/2][f][2] out_w pair-transposed
static __device__ __align__(16) float d_R[BNT*64];    // [bn][t][f]

__device__ __forceinline__ float lrelu(float x){ return x >= 0.f ? x : 0.2f*x; }
__device__ __forceinline__ ull pk2(float a, float b){ ull r; asm("mov.b64 %0,{%1,%2};" : "=l"(r) : "f"(a), "f"(b)); return r; }
__device__ __forceinline__ void fma2(ull& d, ull a, ull b){ asm("fma.rn.f32x2 %0,%1,%2,%0;" : "+l"(d) : "l"(a), "l"(b)); }
__device__ __forceinline__ float2 up2(ull v){ float2 r; asm("mov.b64 {%0,%1},%2;" : "=f"(r.x), "=f"(r.y) : "l"(v)); return r; }

// ---------------- graph preprocessing ----------------
__global__ void k_count(const int* __restrict__ ei){
  int e = blockIdx.x*blockDim.x + threadIdx.x;
  if(e < NE){
    atomicAdd(&d_deg[ei[e]], 1);
    atomicAdd(&d_cnt[ei[NE+e]], 1);
  }
}

// parallel (unordered) CSR segment assignment + deg^{-1/2}
__global__ void k_off(){
  int i = blockIdx.x*blockDim.x + threadIdx.x;
  int lane = threadIdx.x & 31;
  int c = (i < NV) ? d_cnt[i] : 0;
  int pre = c;
  #pragma unroll
  for(int off=1; off<32; off<<=1){
    int v = __shfl_up_sync(0xFFFFFFFFu, pre, off);
    if(lane >= off) pre += v;
  }
  int tot = __shfl_sync(0xFFFFFFFFu, pre, 31);
  int base = 0;
  if(lane == 31) base = atomicAdd(&d_tot, tot);
  base = __shfl_sync(0xFFFFFFFFu, base, 31);
  if(i < NV){
    int start = base + pre - c;
    d_rs[i] = start; d_cursor[i] = start; d_re[i] = start + c;
    int dg = d_deg[i];
    d_dis[i] = (dg > 0) ? 1.0f/sqrtf((float)dg) : 0.0f;
  }
}

__global__ void k_fill(const int* __restrict__ ei){
  int e = blockIdx.x*blockDim.x + threadIdx.x;
  if(e < NE){
    int s = ei[e], d = ei[NE+e];
    float w = -d_dis[s]*d_dis[d];
    int p = atomicAdd(&d_cursor[d], 1);
    d_ewi[p] = make_int2(s*12, __float_as_int(w));
  }
}

// ---------------- weight folding (+ counter zeroing) ----------------
__global__ void k_prep(const float* __restrict__ cheb_w, const float* __restrict__ cheb_b,
                       const float* __restrict__ gat_w,  const float* __restrict__ att_src,
                       const float* __restrict__ att_dst,const float* __restrict__ gat_b,
                       const float* __restrict__ tc_w,   const float* __restrict__ tc_b,
                       const float* __restrict__ in_w,   const float* __restrict__ in_b,
                       const float* __restrict__ outw,
                       const float* __restrict__ bcw,    const float* __restrict__ bcb,
                       const float* __restrict__ fcw,    const float* __restrict__ fcb){
  __shared__ float sV[3][128], sC0[128], sU[6][64], sSb[64], sUW[6*192], sSbW[192];
  int tid = threadIdx.x;
  for(int i=tid; i<NV; i+=256){ d_deg[i] = 0; d_cnt[i] = 0; }
  if(tid == 0) d_tot = 0;
  for(int idx=tid; idx<512; idx+=256){
    int k = idx>>7, r = idx&127;
    const float* wv = (k<3)? &cheb_w[k*64] : cheb_b;
    float s = 0.f;
    for(int c=0;c<64;c++) s += wv[c]*gat_w[r*64+c];
    if(k<3) sV[k][r]=s; else sC0[r]=s;
  }
  __syncthreads();
  if(tid < 16){
    int which = tid/8, k = (tid%8)/2, h = tid%2;
    const float* att = which ? att_dst : att_src;
    const float* vv  = (k<3) ? sV[k] : sC0;
    float s = 0.f;
    for(int c=0;c<64;c++) s += vv[h*64+c]*att[h*64+c];
    d_attc[tid] = s;
  }
  for(int idx=tid; idx<6*64; idx+=256){
    int j = idx/64, c = idx%64, h = j/3, k = j%3;
    sU[j][c] = 0.5f*sV[k][h*64+c];
  }
  if(tid < 64) sSb[tid] = gat_b[tid] + 0.5f*(sC0[tid] + sC0[64+tid]);
  __syncthreads();
  for(int idx=tid; idx<7*192; idx+=256){
    int j = idx/192, od = idx%192, o = od/3, dt = od%3;
    const float* uu = (j<6) ? sU[j] : sSb;
    float s = 0.f;
    for(int c=0;c<64;c++) s += uu[c]*tc_w[o*192 + c*3 + dt];
    if(j<6) sUW[j*192+od] = s; else sSbW[od] = s;
  }
  __syncthreads();
  for(int idx=tid; idx<3456; idx+=256){
    int j = idx%6; int rr = (idx/6)%192; int dt = idx/1152;
    float s = 0.f;
    for(int o=0;o<64;o++) s += in_w[rr*64+o]*sUW[j*192 + o*3 + dt];
    d_P2[idx] = s;
  }
  for(int idx=tid; idx<576; idx+=256){
    int dt = idx/192, r = idx%192;
    float s = 0.f;
    for(int o=0;o<64;o++) s += in_w[r*64+o]*sSbW[o*3+dt];
    d_Cq[idx] = s;
  }
  for(int idx=tid; idx<192; idx+=256){
    float s = in_b[idx];
    for(int o=0;o<64;o++) s += in_w[idx*64+o]*tc_b[o];
    d_Bq[idx] = s;
  }
  // conv weights interleaved: d_cwi[(c*3+dt)*128 + o*2 + j] = (j? fcw : bcw)[o][c][dt]
  for(int idx=tid; idx<24576; idx+=256){
    int j = idx&1, o = (idx>>1)&63, cd = idx>>7;
    int c = cd/3, dt = cd - 3*c;
    d_cwi[idx] = j ? fcw[o*192 + c*3 + dt] : bcw[o*192 + c*3 + dt];
  }
  if(tid < 128) d_cb[tid] = (tid < 64) ? bcb[tid] : fcb[tid-64];
  // out_w pair-transposed
  for(int idx=tid; idx<4096; idx+=256){
    int j = idx&1, rest = idx>>1, f = rest&63, i = rest>>6;
    d_owt[idx] = outw[f*64 + 2*i + j];
  }
}

// ---------------- Cheb prop (t-pairs) ----------------
__global__ void k_prop1(const float* __restrict__ x0){
  int i = blockIdx.x*blockDim.x + threadIdx.x;
  if(i >= BN*6) return;
  int bn = i/6, tp = i - bn*6;
  float sx = 0.f, sy = 0.f;
  if(bn < NV){
    int b = d_rs[bn], en = d_re[bn];
    for(int j=b;j<en;j++){
      int2 er = d_ewi[j];
      float w = __int_as_float(er.y);
      float2 xv = *(const float2*)&x0[er.x + 2*tp];
      sx += w*xv.x; sy += w*xv.y;
    }
  }
  *(float2*)&d_T1[bn*12 + 2*tp] = make_float2(sx, sy);
}

// prop2 + attention logits + pack (fused)
__global__ void k_prop2p(const float* __restrict__ x0){
  int i = blockIdx.x*blockDim.x + threadIdx.x;
  if(i >= BN*6) return;
  int bn = i/6, tp = i - bn*6;
  float sx = 0.f, sy = 0.f;
  if(bn < NV){
    int b = d_rs[bn], en = d_re[bn];
    for(int j=b;j<en;j++){
      int2 er = d_ewi[j];
      float w = __int_as_float(er.y);
      float2 tv = *(const float2*)&d_T1[er.x + 2*tp];
      sx += w*tv.x; sy += w*tv.y;
    }
  }
  int i0 = bn*12 + 2*tp;
  float2 xp  = *(const float2*)&x0[i0];
  float2 t1p = *(const float2*)&d_T1[i0];
  float t2a = 2.f*sx - xp.x, t2b = 2.f*sy - xp.y;
  float4 c0 = *(const float4*)&d_attc[0];
  float4 c1 = *(const float4*)&d_attc[4];
  float4 c2 = *(const float4*)&d_attc[8];
  float4 c3 = *(const float4*)&d_attc[12];
  {
    float t0 = xp.x, t1 = t1p.x, t2 = t2a;
    float aS0 = c1.z + t0*c0.x + t1*c0.z + t2*c1.x;
    float aS1 = c1.w + t0*c0.y + t1*c0.w + t2*c1.y;
    float aD0 = c3.z + t0*c2.x + t1*c2.z + t2*c3.x;
    float aD1 = c3.w + t0*c2.y + t1*c2.w + t2*c3.y;
    d_pack[i0*2+0] = make_float4(aS0, aS1, t0, t1);
    d_pack[i0*2+1] = make_float4(t2, aD0, aD1, 0.f);
  }
  {
    float t0 = xp.y, t1 = t1p.y, t2 = t2b;
    float aS0 = c1.z + t0*c0.x + t1*c0.z + t2*c1.x;
    float aS1 = c1.w + t0*c0.y + t1*c0.w + t2*c1.y;
    float aD0 = c3.z + t0*c2.x + t1*c2.z + t2*c3.x;
    float aD1 = c3.w + t0*c2.y + t1*c2.w + t2*c3.y;
    d_pack[(i0+1)*2+0] = make_float4(aS0, aS1, t0, t1);
    d_pack[(i0+1)*2+1] = make_float4(t2, aD0, aD1, 0.f);
  }
}

// ---------------- GAT: single-pass softmax aggregation ----------------
__global__ void k_gat(){
  int i = blockIdx.x*blockDim.x + threadIdx.x;
  if(i >= BNT) return;
  int bn = i/12, t = i - bn*12;
  float4 pa = d_pack[i*2], pb = d_pack[i*2+1];
  float aD0 = pb.y, aD1 = pb.z;
  float e0 = __expf(lrelu(pa.x + aD0));
  float e1 = __expf(lrelu(pa.y + aD1));
  float z0 = e0, z1 = e1;
  float a00 = e0*pa.z, a01 = e0*pa.w, a02 = e0*pb.x;
  float a10 = e1*pa.z, a11 = e1*pa.w, a12 = e1*pb.x;
  if(bn < NV){
    int b = d_rs[bn], en = d_re[bn];
    for(int j=b;j<en;j++){
      int2 er = d_ewi[j];
      int si = er.x + t;
      float4 na = d_pack[si*2], nb = d_pack[si*2+1];
      float q0 = __expf(lrelu(na.x + aD0));
      float q1 = __expf(lrelu(na.y + aD1));
      z0 += q0; a00 += q0*na.z; a01 += q0*na.w; a02 += q0*nb.x;
      z1 += q1; a10 += q1*na.z; a11 += q1*na.w; a12 += q1*nb.x;
    }
  }
  float iz0 = 1.f/z0, iz1 = 1.f/z1;
  d_G8[i*2+0] = make_float4(a00*iz0, a01*iz0, a02*iz0, a10*iz1);
  d_G8[i*2+1] = make_float4(a11*iz1, a12*iz1, 0.f, 0.f);
}

// ---------------- per-node-group mega kernel (4 nodes/block, dynamic smem) ----------------
__global__ void __launch_bounds__(192,2) k_m1(
    const float* __restrict__ x0,
    const float* __restrict__ outb,const float* __restrict__ resw,
    const float* __restrict__ resb,const float* __restrict__ lng,
    const float* __restrict__ lnb){
  extern __shared__ __align__(16) char dsm[];
  float* qs   = (float*)dsm;
  float* zsh  = (float*)dsm;                 // alias: qs dead after MHA
  float* osh  = (float*)(dsm + 38400);
  float (*a6p)[14][8] = (float(*)[14][8])(dsm + 50688);
  float* xs   = (float*)(dsm + 52480);
  float* mu   = (float*)(dsm + 52672);
  float* rstd = (float*)(dsm + 52864);

  int bn0 = blockIdx.x*NB;
  int tid = threadIdx.x;

  for(int i=tid; i<NB*112; i+=192){
    int n = i/112, rr = (i%112)>>3, col = i&7;
    a6p[n][rr][col] = (rr==0 || rr==13) ? 0.f
                    : ((const float*)d_G8)[(size_t)(bn0+n)*96 + (rr-1)*8 + col];
  }
  if(tid < NB*12) xs[tid] = x0[bn0*12 + tid];

  int r = tid;
  ull P2r[9];
  #pragma unroll
  for(int dt=0;dt<3;dt++)
    #pragma unroll
    for(int jj=0;jj<3;jj++)
      P2r[dt*3+jj] = *(const ull*)&d_P2[(dt*192+r)*6 + jj*2];
  float bq = d_Bq[r], cq0 = d_Cq[r], cq1 = d_Cq[192+r], cq2 = d_Cq[384+r];
  float cB = bq+cq1+cq2, cI = bq+cq0+cq1+cq2, cE = bq+cq0+cq1;
  __syncthreads();

  // qkv: sliding 3-row register window; only 2 LDS.128 per t (row t+2)
  #pragma unroll
  for(int n=0;n<NB;n++){
    const longlong2* rp = (const longlong2*)a6p[n];   // 2 longlong2 per row
    ull A0,A1,A2, B0,B1,B2;
    {
      longlong2 x0v = rp[0], x1v = rp[1];
      A0=(ull)x0v.x; A1=(ull)x0v.y; A2=(ull)x1v.x;
      longlong2 y0v = rp[2], y1v = rp[3];
      B0=(ull)y0v.x; B1=(ull)y0v.y; B2=(ull)y1v.x;
    }
    #pragma unroll
    for(int t=0;t<12;t++){
      longlong2 z0v = rp[(t+2)*2], z1v = rp[(t+2)*2+1];
      ull C0=(ull)z0v.x, C1=(ull)z0v.y, C2=(ull)z1v.x;
      ull acc = 0ULL;
      fma2(acc, P2r[0], A0); fma2(acc, P2r[1], A1); fma2(acc, P2r[2], A2);
      fma2(acc, P2r[3], B0); fma2(acc, P2r[4], B1); fma2(acc, P2r[5], B2);
      fma2(acc, P2r[6], C0); fma2(acc, P2r[7], C1); fma2(acc, P2r[8], C2);
      float2 u = up2(acc);
      qs[n*2400 + t*QST + r] = u.x + u.y + (t==0 ? cB : (t==11 ? cE : cI));
      A0=B0; A1=B1; A2=B2; B0=C0; B1=C1; B2=C2;
    }
  }
  __syncthreads();

  // MHA: 128-bit qs reads
  {
    int n = tid/48, rem = tid%48, h = rem/12, tq = rem%12;
    const float* qbase = &qs[n*2400];
    const longlong2* qv = (const longlong2*)&qbase[tq*QST + h*16];
    ull qr[8];
    #pragma unroll
    for(int d=0;d<4;d++){ longlong2 q = qv[d]; qr[2*d]=(ull)q.x; qr[2*d+1]=(ull)q.y; }
    float sc[12]; float m = -1e30f;
    #pragma unroll
    for(int tk=0;tk<12;tk++){
      const longlong2* kv = (const longlong2*)&qbase[tk*QST + 64 + h*16];
      ull a = 0ULL;
      #pragma unroll
      for(int d=0;d<4;d++){
        longlong2 q = kv[d];
        fma2(a, qr[2*d], (ull)q.x);
        fma2(a, qr[2*d+1], (ull)q.y);
      }
      float2 u = up2(a);
      float s = (u.x+u.y)*0.25f;
      sc[tk] = s; m = fmaxf(m, s);
    }
    float z = 0.f;
    #pragma unroll
    for(int tk=0;tk<12;tk++){ sc[tk] = __expf(sc[tk]-m); z += sc[tk]; }
    float inv = 1.f/z;
    ull o2[8];
    #pragma unroll
    for(int d=0;d<8;d++) o2[d] = 0ULL;
    #pragma unroll
    for(int tk=0;tk<12;tk++){
      ull sp = pk2(sc[tk], sc[tk]);
      const longlong2* vv = (const longlong2*)&qbase[tk*QST + 128 + h*16];
      #pragma unroll
      for(int d=0;d<4;d++){
        longlong2 q = vv[d];
        fma2(o2[2*d], sp, (ull)q.x);
        fma2(o2[2*d+1], sp, (ull)q.y);
      }
    }
    #pragma unroll
    for(int d=0;d<8;d++){
      float2 u = up2(o2[d]);
      *(float2*)&osh[n*768 + tq*64 + h*16 + 2*d] = make_float2(u.x*inv, u.y*inv);
    }
  }

  int f = tid%64, grp = tid/64;
  ull wreg[32];
  #pragma unroll
  for(int i=0;i<32;i++) wreg[i] = *(const ull*)&d_owt[(i*64+f)*2];
  float obf = outb[f], rwf = resw[f], rbf = resb[f];
  __syncthreads();            // MHA done; qs dead -> zsh alias safe

  // out projection: longlong2 loads give aligned reg pairs -> no packing MOVs
  #pragma unroll
  for(int it=0; it<16; it++){
    int pi = grp*16 + it;
    int n = pi/12, t = pi%12;
    const longlong2* op2 = (const longlong2*)&osh[n*768 + t*64];
    ull acc = 0ULL;
    #pragma unroll
    for(int i=0;i<16;i++){
      longlong2 q = op2[i];
      fma2(acc, (ull)q.x, wreg[2*i]);
      fma2(acc, (ull)q.y, wreg[2*i+1]);
    }
    float2 u = up2(acc);
    float v = u.x + u.y + obf + rwf*xs[pi] + rbf;
    zsh[pi*64 + f] = fmaxf(v, 0.f);
  }
  __syncthreads();

  // LN stats: one pass, float4 reads (var = E[x^2]-E[x]^2)
  if(tid < NB*12){
    const float4* zr4 = (const float4*)&zsh[tid*64];
    float s = 0.f, s2 = 0.f;
    #pragma unroll
    for(int i=0;i<16;i++){
      float4 v = zr4[i];
      s  += v.x + v.y + v.z + v.w;
      s2 += v.x*v.x + v.y*v.y + v.z*v.z + v.w*v.w;
    }
    float mm = s*(1.f/64.f);
    float var = s2*(1.f/64.f) - mm*mm;
    mu[tid] = mm; rstd[tid] = rsqrtf(var + 1e-5f);
  }
  __syncthreads();

  float lgf = lng[f], lbf = lnb[f];
  #pragma unroll
  for(int it=0; it<16; it++){
    int pi = grp*16 + it;
    d_R[(size_t)bn0*768 + pi*64 + f] = (zsh[pi*64+f]-mu[pi])*rstd[pi]*lgf + lbf;
  }
}

// ---------------- backcast/forecast convs: (bc,fc) packed in f32x2 halves ----------------
// (R10 proven version) thread = (node nn, channel o). Values duplicated in smem
// -> LDS.64 broadcast, weights pre-interleaved (bc,fc) -> LDG.64. No packing MOVs.
__global__ void __launch_bounds__(256) k_m2(float* __restrict__ out){
  __shared__ __align__(16) float rsd[4*64*30];   // 30720 B
  int tid = threadIdx.x;
  int node0 = blockIdx.x*4;

  {  // zero pad slots (t=-1, t=12)
    int nn = tid>>6, c = tid&63;
    float* rw = &rsd[(nn*64+c)*30];
    *(ull*)&rw[0]  = 0ULL;
    *(ull*)&rw[26] = 0ULL;
  }
  for(int v=tid; v<3072; v+=256){
    int nn = v/768, rm = v-nn*768, t = rm>>6, c = rm&63;
    float q = d_R[(size_t)(node0+nn)*768 + rm];
    *(ull*)&rsd[(nn*64+c)*30 + (t+1)*2] = pk2(q,q);
  }
  __syncthreads();

  int nn = tid>>6, o = tid&63;
  const float* rb = &rsd[nn*1920];
  ull acc[12];
  #pragma unroll
  for(int t=0;t<12;t++) acc[t]=0ULL;

  #pragma unroll 4
  for(int c=0;c<64;c++){
    const ull* wp = (const ull*)&d_cwi[(c*3)*128 + o*2];
    ull w0 = wp[0], w1 = wp[64], w2 = wp[128];
    const ull* vp = (const ull*)&rb[c*30];
    #pragma unroll
    for(int t=0;t<12;t++){
      fma2(acc[t], w0, vp[t]);      // r(t-1)
      fma2(acc[t], w1, vp[t+1]);    // r(t)
      fma2(acc[t], w2, vp[t+2]);    // r(t+1)
    }
  }

  int bn = node0 + nn;
  float b0 = d_cb[o], b1 = d_cb[64+o];
  float oa[12], ob[12];
  #pragma unroll
  for(int t=0;t<12;t++){
    float2 u = up2(acc[t]);
    oa[t] = u.x + b0;
    ob[t] = u.y + b1;
  }
  size_t bcb_ = (size_t)bn*768 + (size_t)o*12;
  size_t fcb_ = (size_t)OFS + bcb_;
  *(float4*)&out[bcb_+0] = make_float4(oa[0],oa[1],oa[2],oa[3]);
  *(float4*)&out[bcb_+4] = make_float4(oa[4],oa[5],oa[6],oa[7]);
  *(float4*)&out[bcb_+8] = make_float4(oa[8],oa[9],oa[10],oa[11]);
  *(float4*)&out[fcb_+0] = make_float4(ob[0],ob[1],ob[2],ob[3]);
  *(float4*)&out[fcb_+4] = make_float4(ob[4],ob[5],ob[6],ob[7]);
  *(float4*)&out[fcb_+8] = make_float4(ob[8],ob[9],ob[10],ob[11]);
}

// ---------------- launch ----------------
extern "C" void kernel_launch(void* const* d_in, const int* in_sizes, int n_in,
                              void* d_out, int out_size){
  const float* x       = (const float*)d_in[0];
  const int*   ei      = (const int*  )d_in[1];
  const float* cheb_w  = (const float*)d_in[2];
  const float* cheb_b  = (const float*)d_in[3];
  const float* gat_w   = (const float*)d_in[4];
  const float* att_src = (const float*)d_in[5];
  const float* att_dst = (const float*)d_in[6];
  const float* gat_b   = (const float*)d_in[7];
  const float* tc_w    = (const float*)d_in[8];
  const float* tc_b    = (const float*)d_in[9];
  const float* in_w    = (const float*)d_in[10];
  const float* in_b    = (const float*)d_in[11];
  const float* out_w   = (const float*)d_in[12];
  const float* out_b   = (const float*)d_in[13];
  const float* res_w   = (const float*)d_in[14];
  const float* res_b   = (const float*)d_in[15];
  const float* ln_g    = (const float*)d_in[16];
  const float* ln_b    = (const float*)d_in[17];
  const float* bc_w    = (const float*)d_in[18];
  const float* bc_b    = (const float*)d_in[19];
  const float* fc_w    = (const float*)d_in[20];
  const float* fc_b    = (const float*)d_in[21];
  float* out = (float*)d_out;

  cudaFuncSetAttribute(k_m1, cudaFuncAttributeMaxDynamicSharedMemorySize, SMEM_M1);

  k_prep  <<<1, 256>>>(cheb_w, cheb_b, gat_w, att_src, att_dst, gat_b,
                       tc_w, tc_b, in_w, in_b, out_w, bc_w, bc_b, fc_w, fc_b);
  k_count <<<(NE +255)/256, 256>>>(ei);
  k_off   <<<(NV +255)/256, 256>>>();
  k_fill  <<<(NE +255)/256, 256>>>(ei);
  k_prop1 <<<(BN*6+255)/256, 256>>>(x);
  k_prop2p<<<(BN*6+255)/256, 256>>>(x);
  k_gat   <<<(BNT+255)/256, 256>>>();
  k_m1    <<<BN/NB, 192, SMEM_M1>>>(x, out_b, res_w, res_b, ln_g, ln_b);
  k_m2    <<<BN/4, 256>>>(out);
}

// round 16
// speedup vs baseline: 1.4960x; 1.1115x over previous
#include <cuda_runtime.h>
#include <cuda_bf16.h>
#include <math.h>

#define BN 40000
#define NV 10000
#define TT 12
#define NE 160000
#define BNT (BN*TT)
#define OFS 30720000
#define NB 4
#define QST 200
#define SMEM_M1 53248
#define SMEM_M2T 49152
typedef unsigned long long ull;
typedef unsigned int u32;

// ---------------- device scratch (static, no allocations) ----------------
static __device__ int   d_deg[NV], d_cnt[NV], d_rs[NV], d_re[NV], d_cursor[NV];
static __device__ int   d_tot;
static __device__ float d_dis[NV];
static __device__ __align__(16) int2  d_ewi[NE];     // {src*12, bitcast(weight)} segment order
static __device__ __align__(16) float d_T1[BNT];
static __device__ __align__(16) float d_attc[16];
static __device__ __align__(16) float4 d_pack[BNT*2]; // {aS0,aS1,T0,T1},{T2,aD0,aD1,0}
static __device__ __align__(16) float4 d_G8[BNT*2];   // {g0..g3},{g4,g5,0,0}
static __device__ __align__(16) float d_P2[3456];     // [dt][r][j] j contiguous
static __device__ __align__(16) float d_Cq[576], d_Bq[192];
static __device__ __align__(16) float d_cb[128];
static __device__ __align__(16) float d_owt[4096];    // [i=c/2][f][2] out_w pair-transposed
static __device__ __align__(16) float d_R[BNT*64];    // [bn][t][f]
static __device__ __align__(16) u32 d_wfh[12288];     // W hi, mma-fragment order
static __device__ __align__(16) u32 d_wfl[12288];     // W lo

__device__ __forceinline__ float lrelu(float x){ return x >= 0.f ? x : 0.2f*x; }
__device__ __forceinline__ ull pk2(float a, float b){ ull r; asm("mov.b64 %0,{%1,%2};" : "=l"(r) : "f"(a), "f"(b)); return r; }
__device__ __forceinline__ void fma2(ull& d, ull a, ull b){ asm("fma.rn.f32x2 %0,%1,%2,%0;" : "+l"(d) : "l"(a), "l"(b)); }
__device__ __forceinline__ float2 up2(ull v){ float2 r; asm("mov.b64 {%0,%1},%2;" : "=f"(r.x), "=f"(r.y) : "l"(v)); return r; }
__device__ __forceinline__ u32 pkbf(float a, float b){
  __nv_bfloat162 h = __floats2bfloat162_rn(a, b);
  return *(u32*)&h;
}
__device__ __forceinline__ void mma16816(float* c, const u32* a, ull b){
  u32 b0 = (u32)b, b1 = (u32)(b>>32);
  asm volatile(
    "mma.sync.aligned.m16n8k16.row.col.f32.bf16.bf16.f32 "
    "{%0,%1,%2,%3},{%4,%5,%6,%7},{%8,%9},{%0,%1,%2,%3};"
    : "+f"(c[0]), "+f"(c[1]), "+f"(c[2]), "+f"(c[3])
    : "r"(a[0]), "r"(a[1]), "r"(a[2]), "r"(a[3]), "r"(b0), "r"(b1));
}

// ---------------- graph preprocessing ----------------
__global__ void k_count(const int* __restrict__ ei){
  int e = blockIdx.x*blockDim.x + threadIdx.x;
  if(e < NE){
    atomicAdd(&d_deg[ei[e]], 1);
    atomicAdd(&d_cnt[ei[NE+e]], 1);
  }
}

__global__ void k_off(){
  int i = blockIdx.x*blockDim.x + threadIdx.x;
  int lane = threadIdx.x & 31;
  int c = (i < NV) ? d_cnt[i] : 0;
  int pre = c;
  #pragma unroll
  for(int off=1; off<32; off<<=1){
    int v = __shfl_up_sync(0xFFFFFFFFu, pre, off);
    if(lane >= off) pre += v;
  }
  int tot = __shfl_sync(0xFFFFFFFFu, pre, 31);
  int base = 0;
  if(lane == 31) base = atomicAdd(&d_tot, tot);
  base = __shfl_sync(0xFFFFFFFFu, base, 31);
  if(i < NV){
    int start = base + pre - c;
    d_rs[i] = start; d_cursor[i] = start; d_re[i] = start + c;
    int dg = d_deg[i];
    d_dis[i] = (dg > 0) ? 1.0f/sqrtf((float)dg) : 0.0f;
  }
}

__global__ void k_fill(const int* __restrict__ ei){
  int e = blockIdx.x*blockDim.x + threadIdx.x;
  if(e < NE){
    int s = ei[e], d = ei[NE+e];
    float w = -d_dis[s]*d_dis[d];
    int p = atomicAdd(&d_cursor[d], 1);
    d_ewi[p] = make_int2(s*12, __float_as_int(w));
  }
}

// ---------------- weight folding (+ counter zeroing) ----------------
__global__ void k_prep(const float* __restrict__ cheb_w, const float* __restrict__ cheb_b,
                       const float* __restrict__ gat_w,  const float* __restrict__ att_src,
                       const float* __restrict__ att_dst,const float* __restrict__ gat_b,
                       const float* __restrict__ tc_w,   const float* __restrict__ tc_b,
                       const float* __restrict__ in_w,   const float* __restrict__ in_b,
                       const float* __restrict__ outw,
                       const float* __restrict__ bcw,    const float* __restrict__ bcb,
                       const float* __restrict__ fcw,    const float* __restrict__ fcb){
  __shared__ float sV[3][128], sC0[128], sU[6][64], sSb[64], sUW[6*192], sSbW[192];
  int tid = threadIdx.x;
  for(int i=tid; i<NV; i+=256){ d_deg[i] = 0; d_cnt[i] = 0; }
  if(tid == 0) d_tot = 0;
  for(int idx=tid; idx<512; idx+=256){
    int k = idx>>7, r = idx&127;
    const float* wv = (k<3)? &cheb_w[k*64] : cheb_b;
    float s = 0.f;
    for(int c=0;c<64;c++) s += wv[c]*gat_w[r*64+c];
    if(k<3) sV[k][r]=s; else sC0[r]=s;
  }
  __syncthreads();
  if(tid < 16){
    int which = tid/8, k = (tid%8)/2, h = tid%2;
    const float* att = which ? att_dst : att_src;
    const float* vv  = (k<3) ? sV[k] : sC0;
    float s = 0.f;
    for(int c=0;c<64;c++) s += vv[h*64+c]*att[h*64+c];
    d_attc[tid] = s;
  }
  for(int idx=tid; idx<6*64; idx+=256){
    int j = idx/64, c = idx%64, h = j/3, k = j%3;
    sU[j][c] = 0.5f*sV[k][h*64+c];
  }
  if(tid < 64) sSb[tid] = gat_b[tid] + 0.5f*(sC0[tid] + sC0[64+tid]);
  __syncthreads();
  for(int idx=tid; idx<7*192; idx+=256){
    int j = idx/192, od = idx%192, o = od/3, dt = od%3;
    const float* uu = (j<6) ? sU[j] : sSb;
    float s = 0.f;
    for(int c=0;c<64;c++) s += uu[c]*tc_w[o*192 + c*3 + dt];
    if(j<6) sUW[j*192+od] = s; else sSbW[od] = s;
  }
  __syncthreads();
  for(int idx=tid; idx<3456; idx+=256){
    int j = idx%6; int rr = (idx/6)%192; int dt = idx/1152;
    float s = 0.f;
    for(int o=0;o<64;o++) s += in_w[rr*64+o]*sUW[j*192 + o*3 + dt];
    d_P2[idx] = s;
  }
  for(int idx=tid; idx<576; idx+=256){
    int dt = idx/192, r = idx%192;
    float s = 0.f;
    for(int o=0;o<64;o++) s += in_w[r*64+o]*sSbW[o*3+dt];
    d_Cq[idx] = s;
  }
  for(int idx=tid; idx<192; idx+=256){
    float s = in_b[idx];
    for(int o=0;o<64;o++) s += in_w[idx*64+o]*tc_b[o];
    d_Bq[idx] = s;
  }
  // W -> mma fragment order (hi/lo bf16). idx = ((wm*12+s)*32+l)*4+r
  for(int idx=tid; idx<12288; idx+=256){
    int wm = idx/1536, rem = idx%1536;
    int s = rem/128, rem2 = rem%128;
    int l = rem2/4, r = rem2%4;
    int row = wm*16 + (l>>2) + (r&1)*8;
    int c0 = s*16 + (l&3)*2 + (r>>1)*8;
    const float* wsrc = (row<64) ? (bcw + row*192) : (fcw + (row-64)*192);
    float w0 = wsrc[c0], w1 = wsrc[c0+1];
    __nv_bfloat16 h0 = __float2bfloat16(w0), h1 = __float2bfloat16(w1);
    float l0 = w0 - __bfloat162float(h0), l1 = w1 - __bfloat162float(h1);
    d_wfh[idx] = pkbf(__bfloat162float(h0), __bfloat162float(h1));
    d_wfl[idx] = pkbf(l0, l1);
  }
  if(tid < 128) d_cb[tid] = (tid < 64) ? bcb[tid] : fcb[tid-64];
  for(int idx=tid; idx<4096; idx+=256){
    int j = idx&1, rest = idx>>1, f = rest&63, i = rest>>6;
    d_owt[idx] = outw[f*64 + 2*i + j];
  }
}

// ---------------- Cheb prop (t-pairs) ----------------
__global__ void k_prop1(const float* __restrict__ x0){
  int i = blockIdx.x*blockDim.x + threadIdx.x;
  if(i >= BN*6) return;
  int bn = i/6, tp = i - bn*6;
  float sx = 0.f, sy = 0.f;
  if(bn < NV){
    int b = d_rs[bn], en = d_re[bn];
    for(int j=b;j<en;j++){
      int2 er = d_ewi[j];
      float w = __int_as_float(er.y);
      float2 xv = *(const float2*)&x0[er.x + 2*tp];
      sx += w*xv.x; sy += w*xv.y;
    }
  }
  *(float2*)&d_T1[bn*12 + 2*tp] = make_float2(sx, sy);
}

__global__ void k_prop2p(const float* __restrict__ x0){
  int i = blockIdx.x*blockDim.x + threadIdx.x;
  if(i >= BN*6) return;
  int bn = i/6, tp = i - bn*6;
  float sx = 0.f, sy = 0.f;
  if(bn < NV){
    int b = d_rs[bn], en = d_re[bn];
    for(int j=b;j<en;j++){
      int2 er = d_ewi[j];
      float w = __int_as_float(er.y);
      float2 tv = *(const float2*)&d_T1[er.x + 2*tp];
      sx += w*tv.x; sy += w*tv.y;
    }
  }
  int i0 = bn*12 + 2*tp;
  float2 xp  = *(const float2*)&x0[i0];
  float2 t1p = *(const float2*)&d_T1[i0];
  float t2a = 2.f*sx - xp.x, t2b = 2.f*sy - xp.y;
  float4 c0 = *(const float4*)&d_attc[0];
  float4 c1 = *(const float4*)&d_attc[4];
  float4 c2 = *(const float4*)&d_attc[8];
  float4 c3 = *(const float4*)&d_attc[12];
  {
    float t0 = xp.x, t1 = t1p.x, t2 = t2a;
    float aS0 = c1.z + t0*c0.x + t1*c0.z + t2*c1.x;
    float aS1 = c1.w + t0*c0.y + t1*c0.w + t2*c1.y;
    float aD0 = c3.z + t0*c2.x + t1*c2.z + t2*c3.x;
    float aD1 = c3.w + t0*c2.y + t1*c2.w + t2*c3.y;
    d_pack[i0*2+0] = make_float4(aS0, aS1, t0, t1);
    d_pack[i0*2+1] = make_float4(t2, aD0, aD1, 0.f);
  }
  {
    float t0 = xp.y, t1 = t1p.y, t2 = t2b;
    float aS0 = c1.z + t0*c0.x + t1*c0.z + t2*c1.x;
    float aS1 = c1.w + t0*c0.y + t1*c0.w + t2*c1.y;
    float aD0 = c3.z + t0*c2.x + t1*c2.z + t2*c3.x;
    float aD1 = c3.w + t0*c2.y + t1*c2.w + t2*c3.y;
    d_pack[(i0+1)*2+0] = make_float4(aS0, aS1, t0, t1);
    d_pack[(i0+1)*2+1] = make_float4(t2, aD0, aD1, 0.f);
  }
}

// ---------------- GAT: single-pass softmax aggregation ----------------
__global__ void k_gat(){
  int i = blockIdx.x*blockDim.x + threadIdx.x;
  if(i >= BNT) return;
  int bn = i/12, t = i - bn*12;
  float4 pa = d_pack[i*2], pb = d_pack[i*2+1];
  float aD0 = pb.y, aD1 = pb.z;
  float e0 = __expf(lrelu(pa.x + aD0));
  float e1 = __expf(lrelu(pa.y + aD1));
  float z0 = e0, z1 = e1;
  float a00 = e0*pa.z, a01 = e0*pa.w, a02 = e0*pb.x;
  float a10 = e1*pa.z, a11 = e1*pa.w, a12 = e1*pb.x;
  if(bn < NV){
    int b = d_rs[bn], en = d_re[bn];
    for(int j=b;j<en;j++){
      int2 er = d_ewi[j];
      int si = er.x + t;
      float4 na = d_pack[si*2], nb = d_pack[si*2+1];
      float q0 = __expf(lrelu(na.x + aD0));
      float q1 = __expf(lrelu(na.y + aD1));
      z0 += q0; a00 += q0*na.z; a01 += q0*na.w; a02 += q0*nb.x;
      z1 += q1; a10 += q1*na.z; a11 += q1*na.w; a12 += q1*nb.x;
    }
  }
  float iz0 = 1.f/z0, iz1 = 1.f/z1;
  d_G8[i*2+0] = make_float4(a00*iz0, a01*iz0, a02*iz0, a10*iz1);
  d_G8[i*2+1] = make_float4(a11*iz1, a12*iz1, 0.f, 0.f);
}

// ---------------- per-node-group mega kernel (R15 version) ----------------
__global__ void __launch_bounds__(192,2) k_m1(
    const float* __restrict__ x0,
    const float* __restrict__ outb,const float* __restrict__ resw,
    const float* __restrict__ resb,const float* __restrict__ lng,
    const float* __restrict__ lnb){
  extern __shared__ __align__(16) char dsm[];
  float* qs   = (float*)dsm;
  float* zsh  = (float*)dsm;                 // alias: qs dead after MHA
  float* osh  = (float*)(dsm + 38400);
  float (*a6p)[14][8] = (float(*)[14][8])(dsm + 50688);
  float* xs   = (float*)(dsm + 52480);
  float* mu   = (float*)(dsm + 52672);
  float* rstd = (float*)(dsm + 52864);

  int bn0 = blockIdx.x*NB;
  int tid = threadIdx.x;

  for(int i=tid; i<NB*112; i+=192){
    int n = i/112, rr = (i%112)>>3, col = i&7;
    a6p[n][rr][col] = (rr==0 || rr==13) ? 0.f
                    : ((const float*)d_G8)[(size_t)(bn0+n)*96 + (rr-1)*8 + col];
  }
  if(tid < NB*12) xs[tid] = x0[bn0*12 + tid];

  int r = tid;
  ull P2r[9];
  #pragma unroll
  for(int dt=0;dt<3;dt++)
    #pragma unroll
    for(int jj=0;jj<3;jj++)
      P2r[dt*3+jj] = *(const ull*)&d_P2[(dt*192+r)*6 + jj*2];
  float bq = d_Bq[r], cq0 = d_Cq[r], cq1 = d_Cq[192+r], cq2 = d_Cq[384+r];
  float cB = bq+cq1+cq2, cI = bq+cq0+cq1+cq2, cE = bq+cq0+cq1;
  __syncthreads();

  // qkv: sliding 3-row register window
  #pragma unroll
  for(int n=0;n<NB;n++){
    const longlong2* rp = (const longlong2*)a6p[n];
    ull A0,A1,A2, B0,B1,B2;
    {
      longlong2 x0v = rp[0], x1v = rp[1];
      A0=(ull)x0v.x; A1=(ull)x0v.y; A2=(ull)x1v.x;
      longlong2 y0v = rp[2], y1v = rp[3];
      B0=(ull)y0v.x; B1=(ull)y0v.y; B2=(ull)y1v.x;
    }
    #pragma unroll
    for(int t=0;t<12;t++){
      longlong2 z0v = rp[(t+2)*2], z1v = rp[(t+2)*2+1];
      ull C0=(ull)z0v.x, C1=(ull)z0v.y, C2=(ull)z1v.x;
      ull acc = 0ULL;
      fma2(acc, P2r[0], A0); fma2(acc, P2r[1], A1); fma2(acc, P2r[2], A2);
      fma2(acc, P2r[3], B0); fma2(acc, P2r[4], B1); fma2(acc, P2r[5], B2);
      fma2(acc, P2r[6], C0); fma2(acc, P2r[7], C1); fma2(acc, P2r[8], C2);
      float2 u = up2(acc);
      qs[n*2400 + t*QST + r] = u.x + u.y + (t==0 ? cB : (t==11 ? cE : cI));
      A0=B0; A1=B1; A2=B2; B0=C0; B1=C1; B2=C2;
    }
  }
  __syncthreads();

  // MHA
  {
    int n = tid/48, rem = tid%48, h = rem/12, tq = rem%12;
    const float* qbase = &qs[n*2400];
    const longlong2* qv = (const longlong2*)&qbase[tq*QST + h*16];
    ull qr[8];
    #pragma unroll
    for(int d=0;d<4;d++){ longlong2 q = qv[d]; qr[2*d]=(ull)q.x; qr[2*d+1]=(ull)q.y; }
    float sc[12]; float m = -1e30f;
    #pragma unroll
    for(int tk=0;tk<12;tk++){
      const longlong2* kv = (const longlong2*)&qbase[tk*QST + 64 + h*16];
      ull a = 0ULL;
      #pragma unroll
      for(int d=0;d<4;d++){
        longlong2 q = kv[d];
        fma2(a, qr[2*d], (ull)q.x);
        fma2(a, qr[2*d+1], (ull)q.y);
      }
      float2 u = up2(a);
      float s = (u.x+u.y)*0.25f;
      sc[tk] = s; m = fmaxf(m, s);
    }
    float z = 0.f;
    #pragma unroll
    for(int tk=0;tk<12;tk++){ sc[tk] = __expf(sc[tk]-m); z += sc[tk]; }
    float inv = 1.f/z;
    ull o2[8];
    #pragma unroll
    for(int d=0;d<8;d++) o2[d] = 0ULL;
    #pragma unroll
    for(int tk=0;tk<12;tk++){
      ull sp = pk2(sc[tk], sc[tk]);
      const longlong2* vv = (const longlong2*)&qbase[tk*QST + 128 + h*16];
      #pragma unroll
      for(int d=0;d<4;d++){
        longlong2 q = vv[d];
        fma2(o2[2*d], sp, (ull)q.x);
        fma2(o2[2*d+1], sp, (ull)q.y);
      }
    }
    #pragma unroll
    for(int d=0;d<8;d++){
      float2 u = up2(o2[d]);
      *(float2*)&osh[n*768 + tq*64 + h*16 + 2*d] = make_float2(u.x*inv, u.y*inv);
    }
  }

  int f = tid%64, grp = tid/64;
  ull wreg[32];
  #pragma unroll
  for(int i=0;i<32;i++) wreg[i] = *(const ull*)&d_owt[(i*64+f)*2];
  float obf = outb[f], rwf = resw[f], rbf = resb[f];
  __syncthreads();

  #pragma unroll
  for(int it=0; it<16; it++){
    int pi = grp*16 + it;
    int n = pi/12, t = pi%12;
    const longlong2* op2 = (const longlong2*)&osh[n*768 + t*64];
    ull acc = 0ULL;
    #pragma unroll
    for(int i=0;i<16;i++){
      longlong2 q = op2[i];
      fma2(acc, (ull)q.x, wreg[2*i]);
      fma2(acc, (ull)q.y, wreg[2*i+1]);
    }
    float2 u = up2(acc);
    float v = u.x + u.y + obf + rwf*xs[pi] + rbf;
    zsh[pi*64 + f] = fmaxf(v, 0.f);
  }
  __syncthreads();

  if(tid < NB*12){
    const float4* zr4 = (const float4*)&zsh[tid*64];
    float s = 0.f, s2 = 0.f;
    #pragma unroll
    for(int i=0;i<16;i++){
      float4 v = zr4[i];
      s  += v.x + v.y + v.z + v.w;
      s2 += v.x*v.x + v.y*v.y + v.z*v.z + v.w*v.w;
    }
    float mm = s*(1.f/64.f);
    float var = s2*(1.f/64.f) - mm*mm;
    mu[tid] = mm; rstd[tid] = rsqrtf(var + 1e-5f);
  }
  __syncthreads();

  float lgf = lng[f], lbf = lnb[f];
  #pragma unroll
  for(int it=0; it<16; it++){
    int pi = grp*16 + it;
    d_R[(size_t)bn0*768 + pi*64 + f] = (zsh[pi*64+f]-mu[pi])*rstd[pi]*lgf + lbf;
  }
}

// ---------------- bc/fc convs via mma.sync (bf16 hi/lo, f32 acc) ----------------
// 16 nodes/block, 4 chunks of 4 nodes (N=48 each). Warp w owns M-tile rows
// [w*16, w*16+16) of the 128-row (bc|fc) output. W fragments held in regs.
// dyn smem: [0,12288) rstage f32; [12288,30720) sBh u32; [30720,49152) sBl u32.
__global__ void __launch_bounds__(256) k_m2t(float* __restrict__ out){
  extern __shared__ __align__(16) char dsm2[];
  float* rstage = (float*)dsm2;
  u32* sBh = (u32*)(dsm2 + 12288);
  u32* sBl = (u32*)(dsm2 + 30720);
  int tid = threadIdx.x, wid = tid>>5, lane = tid&31;
  int node0 = blockIdx.x*16;

  // A fragments (held across all chunks)
  u32 awh[12][4], awl[12][4];
  #pragma unroll
  for(int s=0;s<12;s++){
    uint4 va = *(const uint4*)&d_wfh[((wid*12+s)*32+lane)*4];
    awh[s][0]=va.x; awh[s][1]=va.y; awh[s][2]=va.z; awh[s][3]=va.w;
    uint4 vb = *(const uint4*)&d_wfl[((wid*12+s)*32+lane)*4];
    awl[s][0]=vb.x; awl[s][1]=vb.y; awl[s][2]=vb.z; awl[s][3]=vb.w;
  }

  int row0 = wid*16 + (lane>>2), row1 = row0 + 8;
  float bias0 = d_cb[row0], bias1 = d_cb[row1];
  int conv0 = row0>>6, ol0 = row0&63;
  int conv1 = row1>>6, ol1 = row1&63;

  for(int chunk=0; chunk<4; chunk++){
    int nb = node0 + chunk*4;
    // stage d_R for 4 nodes (contiguous 3072 floats)
    for(int i=tid; i<768; i+=256)
      *(float4*)&rstage[i*4] = *(const float4*)&d_R[(size_t)nb*768 + (size_t)i*4];
    __syncthreads();

    // build B fragments (hi/lo)
    for(int idx=tid; idx<4608; idx+=256){
      int b = idx&1, l = (idx>>1)&31;
      int nt = (idx>>6)%6, s = idx/384;
      int col = nt*8 + (l>>2);
      int nn = col/12, t = col - nn*12;
      int k0 = s*16 + (l&3)*2 + b*8;
      float v0, v1;
      { int c = k0/3, dt = k0-3*c; int tt = t+dt-1;
        v0 = (tt>=0 && tt<12) ? rstage[nn*768 + tt*64 + c] : 0.f; }
      { int k1 = k0+1; int c = k1/3, dt = k1-3*c; int tt = t+dt-1;
        v1 = (tt>=0 && tt<12) ? rstage[nn*768 + tt*64 + c] : 0.f; }
      __nv_bfloat16 h0 = __float2bfloat16(v0), h1 = __float2bfloat16(v1);
      sBh[idx] = pkbf(__bfloat162float(h0), __bfloat162float(h1));
      sBl[idx] = pkbf(v0 - __bfloat162float(h0), v1 - __bfloat162float(h1));
    }
    __syncthreads();

    float acc[6][4];
    #pragma unroll
    for(int nt=0;nt<6;nt++){ acc[nt][0]=0.f; acc[nt][1]=0.f; acc[nt][2]=0.f; acc[nt][3]=0.f; }

    #pragma unroll
    for(int s=0;s<12;s++){
      #pragma unroll
      for(int nt=0;nt<6;nt++){
        ull bh = *(const ull*)&sBh[((s*6+nt)*32+lane)*2];
        ull bl = *(const ull*)&sBl[((s*6+nt)*32+lane)*2];
        mma16816(acc[nt], awh[s], bh);
        mma16816(acc[nt], awh[s], bl);
        mma16816(acc[nt], awl[s], bh);
      }
    }

    // epilogue: pairs (col, col+1) never cross a node (12 even)
    #pragma unroll
    for(int nt=0;nt<6;nt++){
      int col = nt*8 + (lane&3)*2;
      int nn = col/12, t = col - nn*12;
      size_t b0a = (size_t)(conv0 ? OFS : 0) + (size_t)(nb+nn)*768 + (size_t)ol0*12 + t;
      *(float2*)&out[b0a] = make_float2(acc[nt][0]+bias0, acc[nt][1]+bias0);
      size_t b1a = (size_t)(conv1 ? OFS : 0) + (size_t)(nb+nn)*768 + (size_t)ol1*12 + t;
      *(float2*)&out[b1a] = make_float2(acc[nt][2]+bias1, acc[nt][3]+bias1);
    }
    __syncthreads();
  }
}

// ---------------- launch ----------------
extern "C" void kernel_launch(void* const* d_in, const int* in_sizes, int n_in,
                              void* d_out, int out_size){
  const float* x       = (const float*)d_in[0];
  const int*   ei      = (const int*  )d_in[1];
  const float* cheb_w  = (const float*)d_in[2];
  const float* cheb_b  = (const float*)d_in[3];
  const float* gat_w   = (const float*)d_in[4];
  const float* att_src = (const float*)d_in[5];
  const float* att_dst = (const float*)d_in[6];
  const float* gat_b   = (const float*)d_in[7];
  const float* tc_w    = (const float*)d_in[8];
  const float* tc_b    = (const float*)d_in[9];
  const float* in_w    = (const float*)d_in[10];
  const float* in_b    = (const float*)d_in[11];
  const float* out_w   = (const float*)d_in[12];
  const float* out_b   = (const float*)d_in[13];
  const float* res_w   = (const float*)d_in[14];
  const float* res_b   = (const float*)d_in[15];
  const float* ln_g    = (const float*)d_in[16];
  const float* ln_b    = (const float*)d_in[17];
  const float* bc_w    = (const float*)d_in[18];
  const float* bc_b    = (const float*)d_in[19];
  const float* fc_w    = (const float*)d_in[20];
  const float* fc_b    = (const float*)d_in[21];
  float* out = (float*)d_out;

  cudaFuncSetAttribute(k_m1,  cudaFuncAttributeMaxDynamicSharedMemorySize, SMEM_M1);
  cudaFuncSetAttribute(k_m2t, cudaFuncAttributeMaxDynamicSharedMemorySize, SMEM_M2T);

  k_prep  <<<1, 256>>>(cheb_w, cheb_b, gat_w, att_src, att_dst, gat_b,
                       tc_w, tc_b, in_w, in_b, out_w, bc_w, bc_b, fc_w, fc_b);
  k_count <<<(NE +255)/256, 256>>>(ei);
  k_off   <<<(NV +255)/256, 256>>>();
  k_fill  <<<(NE +255)/256, 256>>>(ei);
  k_prop1 <<<(BN*6+255)/256, 256>>>(x);
  k_prop2p<<<(BN*6+255)/256, 256>>>(x);
  k_gat   <<<(BNT+255)/256, 256>>>();
  k_m1    <<<BN/NB, 192, SMEM_M1>>>(x, out_b, res_w, res_b, ln_g, ln_b);
  k_m2t   <<<BN/16, 256, SMEM_M2T>>>(out);
}

// round 17
// speedup vs baseline: 1.6377x; 1.0947x over previous
#include <cuda_runtime.h>
#include <cuda_bf16.h>
#include <math.h>

#define BN 40000
#define NV 10000
#define TT 12
#define NE 160000
#define BNT (BN*TT)
#define OFS 30720000
#define NB 4
#define QST 200
#define SMEM_M1 53248
#define SMEM_M2T 49152
typedef unsigned long long ull;
typedef unsigned int u32;

// ---------------- device scratch (static, no allocations) ----------------
static __device__ int   d_deg[NV], d_cnt[NV], d_rs[NV], d_re[NV], d_cursor[NV];
static __device__ int   d_tot;
static __device__ float d_dis[NV];
static __device__ __align__(16) int2  d_ewi[NE];     // {src*12, bitcast(weight)} segment order
static __device__ __align__(16) float d_T1[BNT];
static __device__ __align__(16) float d_attc[16];
static __device__ __align__(16) float4 d_pack[BNT*2]; // {aS0,aS1,T0,T1},{T2,aD0,aD1,0}
static __device__ __align__(16) float4 d_G8[BNT*2];   // {g0..g3},{g4,g5,0,0}
static __device__ __align__(16) float d_P2[3456];     // [dt][r][j] j contiguous
static __device__ __align__(16) float d_Cq[576], d_Bq[192];
static __device__ __align__(16) float d_cb[128];
static __device__ __align__(16) float d_R[BNT*64];    // [bn][t][f]
static __device__ __align__(16) u32 d_wfh[12288];     // conv W hi, mma-fragment order
static __device__ __align__(16) u32 d_wfl[12288];     // conv W lo
static __device__ __align__(16) u32 d_ofh[2048];      // out_w hi, mma-fragment order
static __device__ __align__(16) u32 d_ofl[2048];      // out_w lo

__device__ __forceinline__ float lrelu(float x){ return x >= 0.f ? x : 0.2f*x; }
__device__ __forceinline__ ull pk2(float a, float b){ ull r; asm("mov.b64 %0,{%1,%2};" : "=l"(r) : "f"(a), "f"(b)); return r; }
__device__ __forceinline__ void fma2(ull& d, ull a, ull b){ asm("fma.rn.f32x2 %0,%1,%2,%0;" : "+l"(d) : "l"(a), "l"(b)); }
__device__ __forceinline__ float2 up2(ull v){ float2 r; asm("mov.b64 {%0,%1},%2;" : "=f"(r.x), "=f"(r.y) : "l"(v)); return r; }
__device__ __forceinline__ u32 pkbf(float a, float b){
  __nv_bfloat162 h = __floats2bfloat162_rn(a, b);
  return *(u32*)&h;
}
__device__ __forceinline__ void mma16816(float* c, const u32* a, ull b){
  u32 b0 = (u32)b, b1 = (u32)(b>>32);
  asm volatile(
    "mma.sync.aligned.m16n8k16.row.col.f32.bf16.bf16.f32 "
    "{%0,%1,%2,%3},{%4,%5,%6,%7},{%8,%9},{%0,%1,%2,%3};"
    : "+f"(c[0]), "+f"(c[1]), "+f"(c[2]), "+f"(c[3])
    : "r"(a[0]), "r"(a[1]), "r"(a[2]), "r"(a[3]), "r"(b0), "r"(b1));
}

// ---------------- graph preprocessing ----------------
__global__ void k_count(const int* __restrict__ ei){
  int e = blockIdx.x*blockDim.x + threadIdx.x;
  if(e < NE){
    atomicAdd(&d_deg[ei[e]], 1);
    atomicAdd(&d_cnt[ei[NE+e]], 1);
  }
}

__global__ void k_off(){
  int i = blockIdx.x*blockDim.x + threadIdx.x;
  int lane = threadIdx.x & 31;
  int c = (i < NV) ? d_cnt[i] : 0;
  int pre = c;
  #pragma unroll
  for(int off=1; off<32; off<<=1){
    int v = __shfl_up_sync(0xFFFFFFFFu, pre, off);
    if(lane >= off) pre += v;
  }
  int tot = __shfl_sync(0xFFFFFFFFu, pre, 31);
  int base = 0;
  if(lane == 31) base = atomicAdd(&d_tot, tot);
  base = __shfl_sync(0xFFFFFFFFu, base, 31);
  if(i < NV){
    int start = base + pre - c;
    d_rs[i] = start; d_cursor[i] = start; d_re[i] = start + c;
    int dg = d_deg[i];
    d_dis[i] = (dg > 0) ? 1.0f/sqrtf((float)dg) : 0.0f;
  }
}

__global__ void k_fill(const int* __restrict__ ei){
  int e = blockIdx.x*blockDim.x + threadIdx.x;
  if(e < NE){
    int s = ei[e], d = ei[NE+e];
    float w = -d_dis[s]*d_dis[d];
    int p = atomicAdd(&d_cursor[d], 1);
    d_ewi[p] = make_int2(s*12, __float_as_int(w));
  }
}

// ---------------- weight folding (+ counter zeroing) ----------------
__global__ void k_prep(const float* __restrict__ cheb_w, const float* __restrict__ cheb_b,
                       const float* __restrict__ gat_w,  const float* __restrict__ att_src,
                       const float* __restrict__ att_dst,const float* __restrict__ gat_b,
                       const float* __restrict__ tc_w,   const float* __restrict__ tc_b,
                       const float* __restrict__ in_w,   const float* __restrict__ in_b,
                       const float* __restrict__ outw,
                       const float* __restrict__ bcw,    const float* __restrict__ bcb,
                       const float* __restrict__ fcw,    const float* __restrict__ fcb){
  __shared__ float sV[3][128], sC0[128], sU[6][64], sSb[64], sUW[6*192], sSbW[192];
  int tid = threadIdx.x;
  for(int i=tid; i<NV; i+=256){ d_deg[i] = 0; d_cnt[i] = 0; }
  if(tid == 0) d_tot = 0;
  for(int idx=tid; idx<512; idx+=256){
    int k = idx>>7, r = idx&127;
    const float* wv = (k<3)? &cheb_w[k*64] : cheb_b;
    float s = 0.f;
    for(int c=0;c<64;c++) s += wv[c]*gat_w[r*64+c];
    if(k<3) sV[k][r]=s; else sC0[r]=s;
  }
  __syncthreads();
  if(tid < 16){
    int which = tid/8, k = (tid%8)/2, h = tid%2;
    const float* att = which ? att_dst : att_src;
    const float* vv  = (k<3) ? sV[k] : sC0;
    float s = 0.f;
    for(int c=0;c<64;c++) s += vv[h*64+c]*att[h*64+c];
    d_attc[tid] = s;
  }
  for(int idx=tid; idx<6*64; idx+=256){
    int j = idx/64, c = idx%64, h = j/3, k = j%3;
    sU[j][c] = 0.5f*sV[k][h*64+c];
  }
  if(tid < 64) sSb[tid] = gat_b[tid] + 0.5f*(sC0[tid] + sC0[64+tid]);
  __syncthreads();
  for(int idx=tid; idx<7*192; idx+=256){
    int j = idx/192, od = idx%192, o = od/3, dt = od%3;
    const float* uu = (j<6) ? sU[j] : sSb;
    float s = 0.f;
    for(int c=0;c<64;c++) s += uu[c]*tc_w[o*192 + c*3 + dt];
    if(j<6) sUW[j*192+od] = s; else sSbW[od] = s;
  }
  __syncthreads();
  for(int idx=tid; idx<3456; idx+=256){
    int j = idx%6; int rr = (idx/6)%192; int dt = idx/1152;
    float s = 0.f;
    for(int o=0;o<64;o++) s += in_w[rr*64+o]*sUW[j*192 + o*3 + dt];
    d_P2[idx] = s;
  }
  for(int idx=tid; idx<576; idx+=256){
    int dt = idx/192, r = idx%192;
    float s = 0.f;
    for(int o=0;o<64;o++) s += in_w[r*64+o]*sSbW[o*3+dt];
    d_Cq[idx] = s;
  }
  for(int idx=tid; idx<192; idx+=256){
    float s = in_b[idx];
    for(int o=0;o<64;o++) s += in_w[idx*64+o]*tc_b[o];
    d_Bq[idx] = s;
  }
  // conv W -> mma fragment order (hi/lo bf16). idx = ((wm*12+s)*32+l)*4+r
  for(int idx=tid; idx<12288; idx+=256){
    int wm = idx/1536, rem = idx%1536;
    int s = rem/128, rem2 = rem%128;
    int l = rem2/4, r = rem2%4;
    int row = wm*16 + (l>>2) + (r&1)*8;
    int c0 = s*16 + (l&3)*2 + (r>>1)*8;
    const float* wsrc = (row<64) ? (bcw + row*192) : (fcw + (row-64)*192);
    float w0 = wsrc[c0], w1 = wsrc[c0+1];
    __nv_bfloat16 h0 = __float2bfloat16(w0), h1 = __float2bfloat16(w1);
    float l0 = w0 - __bfloat162float(h0), l1 = w1 - __bfloat162float(h1);
    d_wfh[idx] = pkbf(__bfloat162float(h0), __bfloat162float(h1));
    d_wfl[idx] = pkbf(l0, l1);
  }
  // out_w -> mma fragment order (hi/lo bf16). idx = ((m*4+s)*32+l)*4+r
  for(int idx=tid; idx<2048; idx+=256){
    int m = idx/512, rem = idx%512;
    int s = rem/128, rem2 = rem%128;
    int l = rem2/4, r = rem2%4;
    int row = m*16 + (l>>2) + (r&1)*8;
    int c0 = s*16 + (l&3)*2 + (r>>1)*8;
    float w0 = outw[row*64 + c0], w1 = outw[row*64 + c0 + 1];
    __nv_bfloat16 h0 = __float2bfloat16(w0), h1 = __float2bfloat16(w1);
    d_ofh[idx] = pkbf(__bfloat162float(h0), __bfloat162float(h1));
    d_ofl[idx] = pkbf(w0 - __bfloat162float(h0), w1 - __bfloat162float(h1));
  }
  if(tid < 128) d_cb[tid] = (tid < 64) ? bcb[tid] : fcb[tid-64];
}

// ---------------- Cheb prop (t-pairs) ----------------
__global__ void k_prop1(const float* __restrict__ x0){
  int i = blockIdx.x*blockDim.x + threadIdx.x;
  if(i >= BN*6) return;
  int bn = i/6, tp = i - bn*6;
  float sx = 0.f, sy = 0.f;
  if(bn < NV){
    int b = d_rs[bn], en = d_re[bn];
    for(int j=b;j<en;j++){
      int2 er = d_ewi[j];
      float w = __int_as_float(er.y);
      float2 xv = *(const float2*)&x0[er.x + 2*tp];
      sx += w*xv.x; sy += w*xv.y;
    }
  }
  *(float2*)&d_T1[bn*12 + 2*tp] = make_float2(sx, sy);
}

__global__ void k_prop2p(const float* __restrict__ x0){
  int i = blockIdx.x*blockDim.x + threadIdx.x;
  if(i >= BN*6) return;
  int bn = i/6, tp = i - bn*6;
  float sx = 0.f, sy = 0.f;
  if(bn < NV){
    int b = d_rs[bn], en = d_re[bn];
    for(int j=b;j<en;j++){
      int2 er = d_ewi[j];
      float w = __int_as_float(er.y);
      float2 tv = *(const float2*)&d_T1[er.x + 2*tp];
      sx += w*tv.x; sy += w*tv.y;
    }
  }
  int i0 = bn*12 + 2*tp;
  float2 xp  = *(const float2*)&x0[i0];
  float2 t1p = *(const float2*)&d_T1[i0];
  float t2a = 2.f*sx - xp.x, t2b = 2.f*sy - xp.y;
  float4 c0 = *(const float4*)&d_attc[0];
  float4 c1 = *(const float4*)&d_attc[4];
  float4 c2 = *(const float4*)&d_attc[8];
  float4 c3 = *(const float4*)&d_attc[12];
  {
    float t0 = xp.x, t1 = t1p.x, t2 = t2a;
    float aS0 = c1.z + t0*c0.x + t1*c0.z + t2*c1.x;
    float aS1 = c1.w + t0*c0.y + t1*c0.w + t2*c1.y;
    float aD0 = c3.z + t0*c2.x + t1*c2.z + t2*c3.x;
    float aD1 = c3.w + t0*c2.y + t1*c2.w + t2*c3.y;
    d_pack[i0*2+0] = make_float4(aS0, aS1, t0, t1);
    d_pack[i0*2+1] = make_float4(t2, aD0, aD1, 0.f);
  }
  {
    float t0 = xp.y, t1 = t1p.y, t2 = t2b;
    float aS0 = c1.z + t0*c0.x + t1*c0.z + t2*c1.x;
    float aS1 = c1.w + t0*c0.y + t1*c0.w + t2*c1.y;
    float aD0 = c3.z + t0*c2.x + t1*c2.z + t2*c3.x;
    float aD1 = c3.w + t0*c2.y + t1*c2.w + t2*c3.y;
    d_pack[(i0+1)*2+0] = make_float4(aS0, aS1, t0, t1);
    d_pack[(i0+1)*2+1] = make_float4(t2, aD0, aD1, 0.f);
  }
}

// ---------------- GAT: single-pass softmax aggregation ----------------
__global__ void k_gat(){
  int i = blockIdx.x*blockDim.x + threadIdx.x;
  if(i >= BNT) return;
  int bn = i/12, t = i - bn*12;
  float4 pa = d_pack[i*2], pb = d_pack[i*2+1];
  float aD0 = pb.y, aD1 = pb.z;
  float e0 = __expf(lrelu(pa.x + aD0));
  float e1 = __expf(lrelu(pa.y + aD1));
  float z0 = e0, z1 = e1;
  float a00 = e0*pa.z, a01 = e0*pa.w, a02 = e0*pb.x;
  float a10 = e1*pa.z, a11 = e1*pa.w, a12 = e1*pb.x;
  if(bn < NV){
    int b = d_rs[bn], en = d_re[bn];
    for(int j=b;j<en;j++){
      int2 er = d_ewi[j];
      int si = er.x + t;
      float4 na = d_pack[si*2], nb = d_pack[si*2+1];
      float q0 = __expf(lrelu(na.x + aD0));
      float q1 = __expf(lrelu(na.y + aD1));
      z0 += q0; a00 += q0*na.z; a01 += q0*na.w; a02 += q0*nb.x;
      z1 += q1; a10 += q1*na.z; a11 += q1*na.w; a12 += q1*nb.x;
    }
  }
  float iz0 = 1.f/z0, iz1 = 1.f/z1;
  d_G8[i*2+0] = make_float4(a00*iz0, a01*iz0, a02*iz0, a10*iz1);
  d_G8[i*2+1] = make_float4(a11*iz1, a12*iz1, 0.f, 0.f);
}

// ---------------- per-node-group mega kernel (mma out-projection) ----------------
// dyn smem: qs [0,38400); osh [38400,50688); a6p [50688,52480); xs [52480,52672);
//           mu [52672,52864); rstd [52864,53056).
// After MHA, qs region is recycled: zsh [0,12288), sBh [12288,18432), sBl [18432,24576).
__global__ void __launch_bounds__(192,3) k_m1(
    const float* __restrict__ x0,
    const float* __restrict__ outb,const float* __restrict__ resw,
    const float* __restrict__ resb,const float* __restrict__ lng,
    const float* __restrict__ lnb){
  extern __shared__ __align__(16) char dsm[];
  float* qs   = (float*)dsm;
  float* zsh  = (float*)dsm;
  u32*   sBh  = (u32*)(dsm + 12288);
  u32*   sBl  = (u32*)(dsm + 18432);
  float* osh  = (float*)(dsm + 38400);
  float (*a6p)[14][8] = (float(*)[14][8])(dsm + 50688);
  float* xs   = (float*)(dsm + 52480);
  float* mu   = (float*)(dsm + 52672);
  float* rstd = (float*)(dsm + 52864);

  int bn0 = blockIdx.x*NB;
  int tid = threadIdx.x;
  int wid = tid>>5, lane = tid&31;

  for(int i=tid; i<NB*112; i+=192){
    int n = i/112, rr = (i%112)>>3, col = i&7;
    a6p[n][rr][col] = (rr==0 || rr==13) ? 0.f
                    : ((const float*)d_G8)[(size_t)(bn0+n)*96 + (rr-1)*8 + col];
  }
  if(tid < NB*12) xs[tid] = x0[bn0*12 + tid];

  int r = tid;
  ull P2r[9];
  #pragma unroll
  for(int dt=0;dt<3;dt++)
    #pragma unroll
    for(int jj=0;jj<3;jj++)
      P2r[dt*3+jj] = *(const ull*)&d_P2[(dt*192+r)*6 + jj*2];
  float bq = d_Bq[r], cq0 = d_Cq[r], cq1 = d_Cq[192+r], cq2 = d_Cq[384+r];
  float cB = bq+cq1+cq2, cI = bq+cq0+cq1+cq2, cE = bq+cq0+cq1;
  __syncthreads();

  // qkv: sliding 3-row register window
  #pragma unroll
  for(int n=0;n<NB;n++){
    const longlong2* rp = (const longlong2*)a6p[n];
    ull A0,A1,A2, B0,B1,B2;
    {
      longlong2 x0v = rp[0], x1v = rp[1];
      A0=(ull)x0v.x; A1=(ull)x0v.y; A2=(ull)x1v.x;
      longlong2 y0v = rp[2], y1v = rp[3];
      B0=(ull)y0v.x; B1=(ull)y0v.y; B2=(ull)y1v.x;
    }
    #pragma unroll
    for(int t=0;t<12;t++){
      longlong2 z0v = rp[(t+2)*2], z1v = rp[(t+2)*2+1];
      ull C0=(ull)z0v.x, C1=(ull)z0v.y, C2=(ull)z1v.x;
      ull acc = 0ULL;
      fma2(acc, P2r[0], A0); fma2(acc, P2r[1], A1); fma2(acc, P2r[2], A2);
      fma2(acc, P2r[3], B0); fma2(acc, P2r[4], B1); fma2(acc, P2r[5], B2);
      fma2(acc, P2r[6], C0); fma2(acc, P2r[7], C1); fma2(acc, P2r[8], C2);
      float2 u = up2(acc);
      qs[n*2400 + t*QST + r] = u.x + u.y + (t==0 ? cB : (t==11 ? cE : cI));
      A0=B0; A1=B1; A2=B2; B0=C0; B1=C1; B2=C2;
    }
  }
  __syncthreads();

  // MHA: 128-bit qs reads
  {
    int n = tid/48, rem = tid%48, h = rem/12, tq = rem%12;
    const float* qbase = &qs[n*2400];
    const longlong2* qv = (const longlong2*)&qbase[tq*QST + h*16];
    ull qr[8];
    #pragma unroll
    for(int d=0;d<4;d++){ longlong2 q = qv[d]; qr[2*d]=(ull)q.x; qr[2*d+1]=(ull)q.y; }
    float sc[12]; float m = -1e30f;
    #pragma unroll
    for(int tk=0;tk<12;tk++){
      const longlong2* kv = (const longlong2*)&qbase[tk*QST + 64 + h*16];
      ull a = 0ULL;
      #pragma unroll
      for(int d=0;d<4;d++){
        longlong2 q = kv[d];
        fma2(a, qr[2*d], (ull)q.x);
        fma2(a, qr[2*d+1], (ull)q.y);
      }
      float2 u = up2(a);
      float s = (u.x+u.y)*0.25f;
      sc[tk] = s; m = fmaxf(m, s);
    }
    float z = 0.f;
    #pragma unroll
    for(int tk=0;tk<12;tk++){ sc[tk] = __expf(sc[tk]-m); z += sc[tk]; }
    float inv = 1.f/z;
    ull o2[8];
    #pragma unroll
    for(int d=0;d<8;d++) o2[d] = 0ULL;
    #pragma unroll
    for(int tk=0;tk<12;tk++){
      ull sp = pk2(sc[tk], sc[tk]);
      const longlong2* vv = (const longlong2*)&qbase[tk*QST + 128 + h*16];
      #pragma unroll
      for(int d=0;d<4;d++){
        longlong2 q = vv[d];
        fma2(o2[2*d], sp, (ull)q.x);
        fma2(o2[2*d+1], sp, (ull)q.y);
      }
    }
    #pragma unroll
    for(int d=0;d<8;d++){
      float2 u = up2(o2[d]);
      *(float2*)&osh[n*768 + tq*64 + h*16 + 2*d] = make_float2(u.x*inv, u.y*inv);
    }
  }
  __syncthreads();   // osh complete; qs dead -> zsh/sB alias safe

  // osh -> B fragments (bf16 hi/lo)
  for(int idx=tid; idx<1536; idx+=192){
    int b = idx&1, l = (idx>>1)&31;
    int nt = (idx>>6)%6, s = idx/384;
    int col = nt*8 + (l>>2);
    int k0 = s*16 + (l&3)*2 + b*8;
    float v0 = osh[col*64 + k0], v1 = osh[col*64 + k0 + 1];
    __nv_bfloat16 h0 = __float2bfloat16(v0), h1 = __float2bfloat16(v1);
    sBh[idx] = pkbf(__bfloat162float(h0), __bfloat162float(h1));
    sBl[idx] = pkbf(v0 - __bfloat162float(h0), v1 - __bfloat162float(h1));
  }
  __syncthreads();

  // out projection via mma (warps 0-3; M-tile = wid)
  if(wid < 4){
    u32 awh[4][4], awl[4][4];
    #pragma unroll
    for(int s=0;s<4;s++){
      uint4 va = *(const uint4*)&d_ofh[((wid*4+s)*32+lane)*4];
      awh[s][0]=va.x; awh[s][1]=va.y; awh[s][2]=va.z; awh[s][3]=va.w;
      uint4 vb = *(const uint4*)&d_ofl[((wid*4+s)*32+lane)*4];
      awl[s][0]=vb.x; awl[s][1]=vb.y; awl[s][2]=vb.z; awl[s][3]=vb.w;
    }
    float acc[6][4];
    #pragma unroll
    for(int nt=0;nt<6;nt++){ acc[nt][0]=0.f; acc[nt][1]=0.f; acc[nt][2]=0.f; acc[nt][3]=0.f; }
    #pragma unroll
    for(int s=0;s<4;s++){
      #pragma unroll
      for(int nt=0;nt<6;nt++){
        ull bh = *(const ull*)&sBh[((s*6+nt)*32+lane)*2];
        ull bl = *(const ull*)&sBl[((s*6+nt)*32+lane)*2];
        mma16816(acc[nt], awh[s], bh);
        mma16816(acc[nt], awh[s], bl);
        mma16816(acc[nt], awl[s], bh);
      }
    }
    int r0 = wid*16 + (lane>>2), r1 = r0 + 8;
    float ob0 = outb[r0], rw0 = resw[r0], rb0 = resb[r0];
    float ob1 = outb[r1], rw1 = resw[r1], rb1 = resb[r1];
    #pragma unroll
    for(int nt=0;nt<6;nt++){
      int col = nt*8 + (lane&3)*2;
      float xc0 = xs[col], xc1 = xs[col+1];
      zsh[col*64 + r0]     = fmaxf(acc[nt][0] + ob0 + rw0*xc0 + rb0, 0.f);
      zsh[(col+1)*64 + r0] = fmaxf(acc[nt][1] + ob0 + rw0*xc1 + rb0, 0.f);
      zsh[col*64 + r1]     = fmaxf(acc[nt][2] + ob1 + rw1*xc0 + rb1, 0.f);
      zsh[(col+1)*64 + r1] = fmaxf(acc[nt][3] + ob1 + rw1*xc1 + rb1, 0.f);
    }
  }
  __syncthreads();

  // LN stats: one pass, float4 reads
  if(tid < NB*12){
    const float4* zr4 = (const float4*)&zsh[tid*64];
    float s = 0.f, s2 = 0.f;
    #pragma unroll
    for(int i=0;i<16;i++){
      float4 v = zr4[i];
      s  += v.x + v.y + v.z + v.w;
      s2 += v.x*v.x + v.y*v.y + v.z*v.z + v.w*v.w;
    }
    float mm = s*(1.f/64.f);
    float var = s2*(1.f/64.f) - mm*mm;
    mu[tid] = mm; rstd[tid] = rsqrtf(var + 1e-5f);
  }
  __syncthreads();

  int f = tid%64, grp = tid/64;
  float lgf = lng[f], lbf = lnb[f];
  #pragma unroll
  for(int it=0; it<16; it++){
    int pi = grp*16 + it;
    d_R[(size_t)bn0*768 + pi*64 + f] = (zsh[pi*64+f]-mu[pi])*rstd[pi]*lgf + lbf;
  }
}

// ---------------- bc/fc convs via mma.sync (R16 proven version) ----------------
__global__ void __launch_bounds__(256) k_m2t(float* __restrict__ out){
  extern __shared__ __align__(16) char dsm2[];
  float* rstage = (float*)dsm2;
  u32* sBh = (u32*)(dsm2 + 12288);
  u32* sBl = (u32*)(dsm2 + 30720);
  int tid = threadIdx.x, wid = tid>>5, lane = tid&31;
  int node0 = blockIdx.x*16;

  u32 awh[12][4], awl[12][4];
  #pragma unroll
  for(int s=0;s<12;s++){
    uint4 va = *(const uint4*)&d_wfh[((wid*12+s)*32+lane)*4];
    awh[s][0]=va.x; awh[s][1]=va.y; awh[s][2]=va.z; awh[s][3]=va.w;
    uint4 vb = *(const uint4*)&d_wfl[((wid*12+s)*32+lane)*4];
    awl[s][0]=vb.x; awl[s][1]=vb.y; awl[s][2]=vb.z; awl[s][3]=vb.w;
  }

  int row0 = wid*16 + (lane>>2), row1 = row0 + 8;
  float bias0 = d_cb[row0], bias1 = d_cb[row1];
  int conv0 = row0>>6, ol0 = row0&63;
  int conv1 = row1>>6, ol1 = row1&63;

  for(int chunk=0; chunk<4; chunk++){
    int nb = node0 + chunk*4;
    for(int i=tid; i<768; i+=256)
      *(float4*)&rstage[i*4] = *(const float4*)&d_R[(size_t)nb*768 + (size_t)i*4];
    __syncthreads();

    for(int idx=tid; idx<4608; idx+=256){
      int b = idx&1, l = (idx>>1)&31;
      int nt = (idx>>6)%6, s = idx/384;
      int col = nt*8 + (l>>2);
      int nn = col/12, t = col - nn*12;
      int k0 = s*16 + (l&3)*2 + b*8;
      float v0, v1;
      { int c = k0/3, dt = k0-3*c; int tt = t+dt-1;
        v0 = (tt>=0 && tt<12) ? rstage[nn*768 + tt*64 + c] : 0.f; }
      { int k1 = k0+1; int c = k1/3, dt = k1-3*c; int tt = t+dt-1;
        v1 = (tt>=0 && tt<12) ? rstage[nn*768 + tt*64 + c] : 0.f; }
      __nv_bfloat16 h0 = __float2bfloat16(v0), h1 = __float2bfloat16(v1);
      sBh[idx] = pkbf(__bfloat162float(h0), __bfloat162float(h1));
      sBl[idx] = pkbf(v0 - __bfloat162float(h0), v1 - __bfloat162float(h1));
    }
    __syncthreads();

    float acc[6][4];
    #pragma unroll
    for(int nt=0;nt<6;nt++){ acc[nt][0]=0.f; acc[nt][1]=0.f; acc[nt][2]=0.f; acc[nt][3]=0.f; }

    #pragma unroll
    for(int s=0;s<12;s++){
      #pragma unroll
      for(int nt=0;nt<6;nt++){
        ull bh = *(const ull*)&sBh[((s*6+nt)*32+lane)*2];
        ull bl = *(const ull*)&sBl[((s*6+nt)*32+lane)*2];
        mma16816(acc[nt], awh[s], bh);
        mma16816(acc[nt], awh[s], bl);
        mma16816(acc[nt], awl[s], bh);
      }
    }

    #pragma unroll
    for(int nt=0;nt<6;nt++){
      int col = nt*8 + (lane&3)*2;
      int nn = col/12, t = col - nn*12;
      size_t b0a = (size_t)(conv0 ? OFS : 0) + (size_t)(nb+nn)*768 + (size_t)ol0*12 + t;
      *(float2*)&out[b0a] = make_float2(acc[nt][0]+bias0, acc[nt][1]+bias0);
      size_t b1a = (size_t)(conv1 ? OFS : 0) + (size_t)(nb+nn)*768 + (size_t)ol1*12 + t;
      *(float2*)&out[b1a] = make_float2(acc[nt][2]+bias1, acc[nt][3]+bias1);
    }
    __syncthreads();
  }
}

// ---------------- launch ----------------
extern "C" void kernel_launch(void* const* d_in, const int* in_sizes, int n_in,
                              void* d_out, int out_size){
  const float* x       = (const float*)d_in[0];
  const int*   ei      = (const int*  )d_in[1];
  const float* cheb_w  = (const float*)d_in[2];
  const float* cheb_b  = (const float*)d_in[3];
  const float* gat_w   = (const float*)d_in[4];
  const float* att_src = (const float*)d_in[5];
  const float* att_dst = (const float*)d_in[6];
  const float* gat_b   = (const float*)d_in[7];
  const float* tc_w    = (const float*)d_in[8];
  const float* tc_b    = (const float*)d_in[9];
  const float* in_w    = (const float*)d_in[10];
  const float* in_b    = (const float*)d_in[11];
  const float* out_w   = (const float*)d_in[12];
  const float* out_b   = (const float*)d_in[13];
  const float* res_w   = (const float*)d_in[14];
  const float* res_b   = (const float*)d_in[15];
  const float* ln_g    = (const float*)d_in[16];
  const float* ln_b    = (const float*)d_in[17];
  const float* bc_w    = (const float*)d_in[18];
  const float* bc_b    = (const float*)d_in[19];
  const float* fc_w    = (const float*)d_in[20];
  const float* fc_b    = (const float*)d_in[21];
  float* out = (float*)d_out;

  cudaFuncSetAttribute(k_m1,  cudaFuncAttributeMaxDynamicSharedMemorySize, SMEM_M1);
  cudaFuncSetAttribute(k_m2t, cudaFuncAttributeMaxDynamicSharedMemorySize, SMEM_M2T);

  k_prep  <<<1, 256>>>(cheb_w, cheb_b, gat_w, att_src, att_dst, gat_b,
                       tc_w, tc_b, in_w, in_b, out_w, bc_w, bc_b, fc_w, fc_b);
  k_count <<<(NE +255)/256, 256>>>(ei);
  k_off   <<<(NV +255)/256, 256>>>();
  k_fill  <<<(NE +255)/256, 256>>>(ei);
  k_prop1 <<<(BN*6+255)/256, 256>>>(x);
  k_prop2p<<<(BN*6+255)/256, 256>>>(x);
  k_gat   <<<(BNT+255)/256, 256>>>();
  k_m1    <<<BN/NB, 192, SMEM_M1>>>(x, out_b, res_w, res_b, ln_g, ln_b);
  k_m2t   <<<BN/16, 256, SMEM_M2T>>>(out);
}